// round 11
// baseline (speedup 1.0000x reference)
#include <cuda_runtime.h>
#include <cuda_bf16.h>
#include <math.h>
#include <stdint.h>

#define NN 100000
#define NE 1600000
#define NF 512
#define FD 128
#define NC 10
#define OUTC 12

// ================= PTX helpers (sm_80-compatible only) =================
__device__ __forceinline__ uint32_t s2u(const void* p) {
    uint32_t a;
    asm("{ .reg .u64 t; cvta.to.shared.u64 t, %1; cvt.u32.u64 %0, t; }"
        : "=r"(a) : "l"(p));
    return a;
}
__device__ __forceinline__ void cpa16(uint32_t dst, const void* src) {
    asm volatile("cp.async.cg.shared.global [%0], [%1], 16;" :: "r"(dst), "l"(src));
}
#define CP_COMMIT() asm volatile("cp.async.commit_group;" ::: "memory")
#define CP_WAIT1()  asm volatile("cp.async.wait_group 1;" ::: "memory")
#define CP_WAIT0()  asm volatile("cp.async.wait_group 0;" ::: "memory")

__device__ __forceinline__ void ldsm4(uint32_t* r, uint32_t addr) {
    asm volatile("ldmatrix.sync.aligned.m8n8.x4.shared.b16 {%0,%1,%2,%3}, [%4];"
                 : "=r"(r[0]), "=r"(r[1]), "=r"(r[2]), "=r"(r[3]) : "r"(addr));
}
__device__ __forceinline__ void mma16816(float* c, const uint32_t* a, const uint32_t* b) {
    asm volatile("mma.sync.aligned.m16n8k16.row.col.f32.bf16.bf16.f32 "
                 "{%0,%1,%2,%3}, {%4,%5,%6,%7}, {%8,%9}, {%0,%1,%2,%3};"
                 : "+f"(c[0]), "+f"(c[1]), "+f"(c[2]), "+f"(c[3])
                 : "r"(a[0]), "r"(a[1]), "r"(a[2]), "r"(a[3]), "r"(b[0]), "r"(b[1]));
}

// ================= scratch (device globals) =================
// P1/P2/G sized 2*NN: rows [0,NN)=good, [NN,2NN)=bad (for the batched W2 GEMM).
__device__ float g_Hg [(size_t)NN * FD];
__device__ float g_G  [(size_t)2 * NN * FD];
__device__ float g_EAf[(size_t)NN * FD];
__device__ float g_T  [(size_t)NN * FD];
__device__ float g_C10[(size_t)NN * NC];
__device__ __nv_bfloat16 g_P1h[(size_t)2 * NN * FD];
__device__ __nv_bfloat16 g_P1l[(size_t)2 * NN * FD];
__device__ __nv_bfloat16 g_P2h[(size_t)2 * NN * FD];
__device__ __nv_bfloat16 g_P2l[(size_t)2 * NN * FD];
__device__ __nv_bfloat16 g_P3h[(size_t)NN * FD];
__device__ __nv_bfloat16 g_P3l[(size_t)NN * FD];
__device__ __nv_bfloat16 g_P4h[(size_t)NN * FD];
__device__ __nv_bfloat16 g_P4l[(size_t)NN * FD];
#define WOFF_W1 0
#define WOFF_W2 (128 * 512)
#define WOFF_W3 (WOFF_W2 + 128 * 128)
#define WOFF_M1 (WOFF_W3 + 128 * 128)
#define WOFF_M2 (WOFF_M1 + 128 * 128)
#define WOFF_WD (WOFF_M2 + 128 * 128)
#define WTOT    (WOFF_WD + 128 * 128)
__device__ __nv_bfloat16 g_Wh[WTOT];
__device__ __nv_bfloat16 g_Wl[WTOT];
__device__ int   g_cnt [2 * NN];
__device__ float g_dis [2 * NN];
__device__ float g_invd[2 * NN];
__device__ int   g_off [2 * (NN + 1)];
__device__ int   g_cur [2 * NN];
__device__ int   g_btot[2 * 128];
__device__ int   g_ssrc[2 * NE];
__device__ int   g_ssrcp[NE];
__device__ float g_sw  [2 * NE];

// ================= CSR build =================
__global__ void k_count(const int* __restrict__ dst, int* __restrict__ cnt) {
    int i = blockIdx.x * blockDim.x + threadIdx.x;
    if (i < NE) atomicAdd(&cnt[dst[i]], 1);
}

__global__ void k_deg(const int* __restrict__ cnt, float* __restrict__ dis,
                      float* __restrict__ invd) {
    int i = blockIdx.x * blockDim.x + threadIdx.x;
    if (i < NN) {
        float d = (float)(cnt[i] + 1);
        dis[i]  = rsqrtf(d);
        invd[i] = 1.0f / d;
    }
}

// ---- multi-block scan ----
#define SCB 1024
__global__ void k_scan_blk(const int* __restrict__ cnt, int* __restrict__ off,
                           int* __restrict__ btot, int n) {
    __shared__ int ws[32];
    const unsigned FULL = 0xffffffffu;
    int t = threadIdx.x, w = t >> 5, l = t & 31;
    int i = blockIdx.x * SCB + t;
    int v = (i < n) ? cnt[i] : 0;
    int s = v;
    #pragma unroll
    for (int d = 1; d < 32; d <<= 1) {
        int o = __shfl_up_sync(FULL, s, d);
        if (l >= d) s += o;
    }
    if (l == 31) ws[w] = s;
    __syncthreads();
    if (w == 0) {
        int x2 = ws[l];
        #pragma unroll
        for (int d = 1; d < 32; d <<= 1) {
            int o = __shfl_up_sync(FULL, x2, d);
            if (l >= d) x2 += o;
        }
        ws[l] = x2;
    }
    __syncthreads();
    int incl = s + (w > 0 ? ws[w - 1] : 0);
    if (i < n) off[i] = incl - v;
    if (t == SCB - 1) btot[blockIdx.x] = incl;
}

__global__ void k_scan_tot(int* __restrict__ btot, int nb, int* __restrict__ offN) {
    __shared__ int sh[128];
    int t = threadIdx.x;
    int v = (t < nb) ? btot[t] : 0;
    sh[t] = v;
    __syncthreads();
    #pragma unroll
    for (int d = 1; d < 128; d <<= 1) {
        int o = (t >= d) ? sh[t - d] : 0;
        __syncthreads();
        sh[t] += o;
        __syncthreads();
    }
    if (t < nb) btot[t] = sh[t] - v;
    if (t == 127) *offN = sh[127];
}

__global__ void k_scan_add(int* __restrict__ off, const int* __restrict__ btot,
                           int* __restrict__ cur, int n) {
    int i = blockIdx.x * blockDim.x + threadIdx.x;
    if (i < n) {
        int e = off[i] + btot[i >> 10];
        off[i] = e;
        cur[i] = e;
    }
}

// place with optional fused permuted-source output
__global__ void k_place(const int* __restrict__ src, const int* __restrict__ dst,
                        const float* __restrict__ dis, int* __restrict__ cur,
                        int* __restrict__ ssrc, float* __restrict__ sw,
                        const int* __restrict__ perm, int* __restrict__ ssrcp) {
    int e = blockIdx.x * blockDim.x + threadIdx.x;
    if (e < NE) {
        int s = src[e], d = dst[e];
        int p = atomicAdd(&cur[d], 1);
        ssrc[p] = s;
        sw[p]   = dis[s] * dis[d];
        if (ssrcp) ssrcp[p] = perm[s];
    }
}

// ================= weight prep =================
__global__ void k_prepw(const float* __restrict__ W, __nv_bfloat16* __restrict__ Bh,
                        __nv_bfloat16* __restrict__ Bl, int K) {
    int i = blockIdx.x * blockDim.x + threadIdx.x;
    if (i < K * 128) {
        int n = i / K, k = i - n * K;
        float v = W[(size_t)k * 128 + n];
        __nv_bfloat16 h = __float2bfloat16(v);
        Bh[(size_t)n * K + k] = h;
        Bl[(size_t)n * K + k] = __float2bfloat16(v - __bfloat162float(h));
    }
}

// ================= mma.sync split-bf16 GEMM =================
#define STRIDE_B 80
#define ARR_SZ   (128 * STRIDE_B)
#define STAGE_SZ (4 * ARR_SZ)
#define SMEM_SZ  (2 * STAGE_SZ)

__device__ __forceinline__ void wmma_prefetch(
    uint32_t sbase, const __nv_bfloat16* Ah, const __nv_bfloat16* Al,
    const __nv_bfloat16* Bh, const __nv_bfloat16* Bl,
    int m0, int M, int K, int k0, int tid)
{
    #pragma unroll
    for (int p = 0; p < 2; p++) {
        int idx = tid + p * 256;
        int row = idx >> 2, cg = idx & 3;
        int gr = m0 + row; if (gr >= M) gr = M - 1;
        size_t aoff = (size_t)gr * K + k0 + cg * 8;
        size_t boff = (size_t)row * K + k0 + cg * 8;
        uint32_t so = row * STRIDE_B + cg * 16;
        cpa16(sbase + 0 * ARR_SZ + so, Ah + aoff);
        cpa16(sbase + 1 * ARR_SZ + so, Al + aoff);
        cpa16(sbase + 2 * ARR_SZ + so, Bh + boff);
        cpa16(sbase + 3 * ARR_SZ + so, Bl + boff);
    }
}

#define WMMA_MAINLOOP_BODY(st)                                                   \
    {                                                                            \
        _Pragma("unroll")                                                        \
        for (int kk = 0; kk < 2; kk++) {                                         \
            const uint32_t kb = kk * 32;                                         \
            uint32_t ah[2][4], al[2][4], bh[4][4], bl[4][4];                     \
            _Pragma("unroll")                                                    \
            for (int mt = 0; mt < 2; mt++) {                                     \
                uint32_t ao = (st) + aoffs + mt * (16 * STRIDE_B) + kb;          \
                ldsm4(ah[mt], ao + 0 * ARR_SZ);                                  \
                ldsm4(al[mt], ao + 1 * ARR_SZ);                                  \
            }                                                                    \
            _Pragma("unroll")                                                    \
            for (int np = 0; np < 4; np++) {                                     \
                uint32_t bo = (st) + boffs + np * (16 * STRIDE_B) + kb;          \
                ldsm4(bh[np], bo + 2 * ARR_SZ);                                  \
                ldsm4(bl[np], bo + 3 * ARR_SZ);                                  \
            }                                                                    \
            _Pragma("unroll")                                                    \
            for (int mt = 0; mt < 2; mt++)                                       \
                _Pragma("unroll")                                                \
                for (int nt = 0; nt < 8; nt++) {                                 \
                    float* cc = c[mt][nt];                                       \
                    const uint32_t* ph = &bh[nt >> 1][(nt & 1) * 2];             \
                    const uint32_t* pl = &bl[nt >> 1][(nt & 1) * 2];             \
                    mma16816(cc, ah[mt], ph);                                    \
                    mma16816(cc, ah[mt], pl);                                    \
                    mma16816(cc, al[mt], ph);                                    \
                }                                                                \
        }                                                                        \
    }

#define WMMA_EPILOGUE()                                                          \
    _Pragma("unroll")                                                            \
    for (int mt = 0; mt < 2; mt++) {                                             \
        _Pragma("unroll")                                                        \
        for (int part = 0; part < 2; part++) {                                   \
            int gr = m0 + wm0 + mt * 16 + (lane >> 2) + part * 8;                \
            if (gr >= M) continue;                                               \
            _Pragma("unroll")                                                    \
            for (int nt = 0; nt < 8; nt++) {                                     \
                int gcol = wn0 + nt * 8 + (lane & 3) * 2;                        \
                float v0 = c[mt][nt][part * 2 + 0];                              \
                float v1 = c[mt][nt][part * 2 + 1];                              \
                if (bias) { v0 += bias[gcol]; v1 += bias[gcol + 1]; }            \
                if (dorelu) { v0 = fmaxf(v0, 0.f); v1 = fmaxf(v1, 0.f); }        \
                if (Cf)                                                          \
                    *(float2*)(Cf + (size_t)gr * FD + gcol) = make_float2(v0, v1); \
                if (Chi) {                                                       \
                    __nv_bfloat16 h0 = __float2bfloat16(v0);                     \
                    __nv_bfloat16 h1 = __float2bfloat16(v1);                     \
                    __nv_bfloat162 hp = __halves2bfloat162(h0, h1);              \
                    __nv_bfloat162 lp = __halves2bfloat162(                      \
                        __float2bfloat16(v0 - __bfloat162float(h0)),             \
                        __float2bfloat16(v1 - __bfloat162float(h1)));            \
                    *(uint32_t*)(Chi + (size_t)gr * FD + gcol) = *(uint32_t*)&hp; \
                    *(uint32_t*)(Clo + (size_t)gr * FD + gcol) = *(uint32_t*)&lp; \
                }                                                                \
            }                                                                    \
        }                                                                        \
    }

__global__ void __launch_bounds__(256, 2) k_wmma(
    const __nv_bfloat16* __restrict__ Ahi, const __nv_bfloat16* __restrict__ Alo,
    const __nv_bfloat16* __restrict__ Bhi, const __nv_bfloat16* __restrict__ Blo,
    const float* __restrict__ bias, int dorelu,
    float* __restrict__ Cf, __nv_bfloat16* __restrict__ Chi,
    __nv_bfloat16* __restrict__ Clo, int M, int K)
{
    extern __shared__ char smem[];
    const uint32_t sb = s2u(smem);
    const int tid  = threadIdx.x;
    const int lane = tid & 31, w = tid >> 5;
    const int wm0 = (w >> 1) * 32, wn0 = (w & 1) * 64;
    const int m0  = blockIdx.x * 128;

    float c[2][8][4];
    #pragma unroll
    for (int i = 0; i < 2; i++)
        #pragma unroll
        for (int j = 0; j < 8; j++)
            #pragma unroll
            for (int q = 0; q < 4; q++) c[i][j][q] = 0.f;

    const uint32_t aoffs = (uint32_t)((wm0 + (lane & 15)) * STRIDE_B + (lane >> 4) * 16);
    const uint32_t boffs = (uint32_t)((wn0 + ((lane >> 4) & 1) * 8 + (lane & 7)) * STRIDE_B
                                      + ((lane >> 3) & 1) * 16);

    const int nch = K >> 5;
    wmma_prefetch(sb, Ahi, Alo, Bhi, Blo, m0, M, K, 0, tid);
    CP_COMMIT();

    for (int ch = 0; ch < nch; ch++) {
        if (ch + 1 < nch) {
            wmma_prefetch(sb + ((ch + 1) & 1) * STAGE_SZ, Ahi, Alo, Bhi, Blo,
                          m0, M, K, (ch + 1) << 5, tid);
            CP_COMMIT();
            CP_WAIT1();
        } else {
            CP_WAIT0();
        }
        __syncthreads();
        const uint32_t st = sb + (ch & 1) * STAGE_SZ;
        WMMA_MAINLOOP_BODY(st)
        __syncthreads();
    }
    WMMA_EPILOGUE()
}

// ---- variant: A is f32, split to hi/lo on the fly (for x @ W1) ----
__global__ void __launch_bounds__(256, 2) k_wmmaX(
    const float* __restrict__ Af,
    const __nv_bfloat16* __restrict__ Bhi, const __nv_bfloat16* __restrict__ Blo,
    const float* __restrict__ bias, int dorelu,
    float* __restrict__ Cf, __nv_bfloat16* __restrict__ Chi,
    __nv_bfloat16* __restrict__ Clo, int M, int K)
{
    extern __shared__ char smem[];
    const uint32_t sb = s2u(smem);
    const int tid  = threadIdx.x;
    const int lane = tid & 31, w = tid >> 5;
    const int wm0 = (w >> 1) * 32, wn0 = (w & 1) * 64;
    const int m0  = blockIdx.x * 128;

    float c[2][8][4];
    #pragma unroll
    for (int i = 0; i < 2; i++)
        #pragma unroll
        for (int j = 0; j < 8; j++)
            #pragma unroll
            for (int q = 0; q < 4; q++) c[i][j][q] = 0.f;

    const uint32_t aoffs = (uint32_t)((wm0 + (lane & 15)) * STRIDE_B + (lane >> 4) * 16);
    const uint32_t boffs = (uint32_t)((wn0 + ((lane >> 4) & 1) * 8 + (lane & 7)) * STRIDE_B
                                      + ((lane >> 3) & 1) * 16);

    const int nch = K >> 5;

    #define PREFETCH_X(sbase, k0)                                                 \
    {                                                                             \
        _Pragma("unroll")                                                         \
        for (int p = 0; p < 2; p++) {                                             \
            int idx = tid + p * 256;                                              \
            int row = idx >> 2, cg = idx & 3;                                     \
            int gr = m0 + row; if (gr >= M) gr = M - 1;                           \
            size_t aoff = (size_t)gr * K + (k0) + cg * 8;                         \
            size_t boff = (size_t)row * K + (k0) + cg * 8;                        \
            uint32_t so = row * STRIDE_B + cg * 16;                               \
            cpa16((sbase) + 2 * ARR_SZ + so, Bhi + boff);                         \
            cpa16((sbase) + 3 * ARR_SZ + so, Blo + boff);                         \
            float4 v0 = *(const float4*)(Af + aoff);                              \
            float4 v1 = *(const float4*)(Af + aoff + 4);                          \
            float vv[8] = {v0.x, v0.y, v0.z, v0.w, v1.x, v1.y, v1.z, v1.w};       \
            uint32_t hw[4], lw[4];                                                \
            _Pragma("unroll")                                                     \
            for (int q = 0; q < 4; q++) {                                         \
                __nv_bfloat16 h0 = __float2bfloat16(vv[2 * q]);                   \
                __nv_bfloat16 h1 = __float2bfloat16(vv[2 * q + 1]);               \
                __nv_bfloat162 hp = __halves2bfloat162(h0, h1);                   \
                __nv_bfloat162 lp = __halves2bfloat162(                           \
                    __float2bfloat16(vv[2 * q] - __bfloat162float(h0)),           \
                    __float2bfloat16(vv[2 * q + 1] - __bfloat162float(h1)));      \
                hw[q] = *(uint32_t*)&hp;                                          \
                lw[q] = *(uint32_t*)&lp;                                          \
            }                                                                     \
            asm volatile("st.shared.v4.b32 [%0], {%1,%2,%3,%4};"                  \
                :: "r"((sbase) + 0 * ARR_SZ + so),                                \
                   "r"(hw[0]), "r"(hw[1]), "r"(hw[2]), "r"(hw[3]) : "memory");    \
            asm volatile("st.shared.v4.b32 [%0], {%1,%2,%3,%4};"                  \
                :: "r"((sbase) + 1 * ARR_SZ + so),                                \
                   "r"(lw[0]), "r"(lw[1]), "r"(lw[2]), "r"(lw[3]) : "memory");    \
        }                                                                         \
    }

    PREFETCH_X(sb, 0)
    CP_COMMIT();

    for (int ch = 0; ch < nch; ch++) {
        if (ch + 1 < nch) {
            PREFETCH_X(sb + ((ch + 1) & 1) * STAGE_SZ, (ch + 1) << 5)
            CP_COMMIT();
            CP_WAIT1();
        } else {
            CP_WAIT0();
        }
        __syncthreads();
        const uint32_t st = sb + (ch & 1) * STAGE_SZ;
        WMMA_MAINLOOP_BODY(st)
        __syncthreads();
    }
    WMMA_EPILOGUE()
    #undef PREFETCH_X
}

// ================= gather aggregation (128-dim, warp/node) =================
__global__ void k_agg(const float* __restrict__ h, const int* __restrict__ off,
                      const int* __restrict__ ssrc, const float* __restrict__ sw,
                      const float* __restrict__ invd, const float* __restrict__ bias,
                      const int* __restrict__ selfmap,
                      float* __restrict__ outf, __nv_bfloat16* __restrict__ outhi,
                      __nv_bfloat16* __restrict__ outlo, int dorelu)
{
    int node = (blockIdx.x * blockDim.x + threadIdx.x) >> 5;
    int lane = threadIdx.x & 31;
    if (node >= NN) return;
    int s = off[node], e = off[node + 1];
    float4 acc = make_float4(0.f, 0.f, 0.f, 0.f);
    for (int i = s; i < e; i++) {
        int   src = ssrc[i];
        float w   = sw[i];
        float4 v  = *(const float4*)(h + (size_t)src * FD + lane * 4);
        acc.x = fmaf(w, v.x, acc.x);
        acc.y = fmaf(w, v.y, acc.y);
        acc.z = fmaf(w, v.z, acc.z);
        acc.w = fmaf(w, v.w, acc.w);
    }
    int self = selfmap ? selfmap[node] : node;
    float  id = invd[node];
    float4 hv = *(const float4*)(h + (size_t)self * FD + lane * 4);
    float4 b  = *(const float4*)(bias + lane * 4);
    acc.x = fmaf(id, hv.x, acc.x) + b.x;
    acc.y = fmaf(id, hv.y, acc.y) + b.y;
    acc.z = fmaf(id, hv.z, acc.z) + b.z;
    acc.w = fmaf(id, hv.w, acc.w) + b.w;
    if (dorelu) {
        acc.x = fmaxf(acc.x, 0.f); acc.y = fmaxf(acc.y, 0.f);
        acc.z = fmaxf(acc.z, 0.f); acc.w = fmaxf(acc.w, 0.f);
    }
    if (outf)
        *(float4*)(outf + (size_t)node * FD + lane * 4) = acc;
    if (outhi) {
        float vv[4] = {acc.x, acc.y, acc.z, acc.w};
        uint32_t hw[2], lw[2];
        #pragma unroll
        for (int q = 0; q < 2; q++) {
            __nv_bfloat16 ha = __float2bfloat16(vv[2 * q]);
            __nv_bfloat16 hb = __float2bfloat16(vv[2 * q + 1]);
            __nv_bfloat162 hp = __halves2bfloat162(ha, hb);
            __nv_bfloat162 lp = __halves2bfloat162(
                __float2bfloat16(vv[2 * q] - __bfloat162float(ha)),
                __float2bfloat16(vv[2 * q + 1] - __bfloat162float(hb)));
            hw[q] = *(uint32_t*)&hp;
            lw[q] = *(uint32_t*)&lp;
        }
        *(uint2*)(outhi + (size_t)node * FD + lane * 4) = make_uint2(hw[0], hw[1]);
        *(uint2*)(outlo + (size_t)node * FD + lane * 4) = make_uint2(lw[0], lw[1]);
    }
}

// ===== fused hop-agg + bilinear score =====
__global__ void k_aggscore(const float* __restrict__ G, const float* __restrict__ T,
                           const int* __restrict__ off, const int* __restrict__ ssrc,
                           const float* __restrict__ sw, const float* __restrict__ invd,
                           const float* __restrict__ b3, float* __restrict__ out,
                           int col)
{
    const unsigned FULL = 0xffffffffu;
    int node = (blockIdx.x * blockDim.x + threadIdx.x) >> 5;
    int lane = threadIdx.x & 31;
    if (node >= NN) return;
    float4 tv = *(const float4*)(T + (size_t)node * FD + lane * 4);
    int s = off[node], e = off[node + 1];
    float acc = 0.f;
    for (int i = s; i < e; i++) {
        int   src = ssrc[i];
        float w   = sw[i];
        float4 v  = *(const float4*)(G + (size_t)src * FD + lane * 4);
        acc = fmaf(w, tv.x * v.x + tv.y * v.y + tv.z * v.z + tv.w * v.w, acc);
    }
    float4 gs = *(const float4*)(G + (size_t)node * FD + lane * 4);
    float4 bb = *(const float4*)(b3 + lane * 4);
    acc = fmaf(invd[node], tv.x * gs.x + tv.y * gs.y + tv.z * gs.z + tv.w * gs.w, acc);
    acc += tv.x * bb.x + tv.y * bb.y + tv.z * bb.z + tv.w * bb.w;
    #pragma unroll
    for (int d = 16; d > 0; d >>= 1) acc += __shfl_xor_sync(FULL, acc, d);
    if (lane == 0)
        out[(size_t)node * OUTC + col] = 1.0f / (1.0f + expf(-acc));
}

// ================= classifier =================
__global__ void k_gemm10(const float* __restrict__ A, const float* __restrict__ W,
                         float* __restrict__ C)
{
    __shared__ float w[FD * NC];
    for (int i = threadIdx.x; i < FD * NC; i += blockDim.x) w[i] = W[i];
    __syncthreads();
    int r = blockIdx.x * blockDim.x + threadIdx.x;
    if (r >= NN) return;
    float acc[NC];
    #pragma unroll
    for (int j = 0; j < NC; j++) acc[j] = 0.f;
    const float4* ap = (const float4*)(A + (size_t)r * FD);
    #pragma unroll 8
    for (int k4 = 0; k4 < 32; k4++) {
        float4 v = ap[k4];
        int k = k4 * 4;
        #pragma unroll
        for (int j = 0; j < NC; j++) {
            acc[j] = fmaf(v.x, w[(k + 0) * NC + j], acc[j]);
            acc[j] = fmaf(v.y, w[(k + 1) * NC + j], acc[j]);
            acc[j] = fmaf(v.z, w[(k + 2) * NC + j], acc[j]);
            acc[j] = fmaf(v.w, w[(k + 3) * NC + j], acc[j]);
        }
    }
    #pragma unroll
    for (int j = 0; j < NC; j++) C[(size_t)r * NC + j] = acc[j];
}

__global__ void k_agg10(const float* __restrict__ h, const int* __restrict__ off,
                        const int* __restrict__ ssrc, const float* __restrict__ sw,
                        const float* __restrict__ invd, const float* __restrict__ bc,
                        float* __restrict__ out)
{
    int node = (blockIdx.x * blockDim.x + threadIdx.x) >> 5;
    int lane = threadIdx.x & 31;
    if (node >= NN || lane >= NC) return;
    int s = off[node], e = off[node + 1];
    float acc = 0.f;
    for (int i = s; i < e; i++) {
        int src = ssrc[i];
        acc = fmaf(sw[i], h[(size_t)src * NC + lane], acc);
    }
    acc = fmaf(invd[node], h[(size_t)node * NC + lane], acc) + bc[lane];
    out[(size_t)node * OUTC + lane] = acc;
}

// ================= host =================
extern "C" void kernel_launch(void* const* d_in, const int* in_sizes, int n_in,
                              void* d_out, int out_size)
{
    const float* x    = (const float*)d_in[0];
    const int*   ei   = (const int*)  d_in[1];
    const int*   eh   = (const int*)  d_in[2];
    const int*   perm = (const int*)  d_in[4];
    const float* W1   = (const float*)d_in[5];
    const float* b1   = (const float*)d_in[6];
    const float* W2   = (const float*)d_in[7];
    const float* b2   = (const float*)d_in[8];
    const float* W3   = (const float*)d_in[9];
    const float* b3   = (const float*)d_in[10];
    const float* M1   = (const float*)d_in[11];
    const float* mb1  = (const float*)d_in[12];
    const float* M2   = (const float*)d_in[13];
    const float* mb2  = (const float*)d_in[14];
    const float* Wc   = (const float*)d_in[15];
    const float* bc   = (const float*)d_in[16];
    const float* Wd   = (const float*)d_in[17];
    float* out = (float*)d_out;

    float *Hg, *G, *EAf, *T, *C10, *dis, *invd, *sw;
    __nv_bfloat16 *P1h, *P1l, *P2h, *P2l, *P3h, *P3l, *P4h, *P4l, *Wh, *Wl;
    int *cnt, *off, *cur, *btot, *ssrc, *ssrcp;
    cudaGetSymbolAddress((void**)&Hg,   g_Hg);
    cudaGetSymbolAddress((void**)&G,    g_G);
    cudaGetSymbolAddress((void**)&EAf,  g_EAf);
    cudaGetSymbolAddress((void**)&T,    g_T);
    cudaGetSymbolAddress((void**)&C10,  g_C10);
    cudaGetSymbolAddress((void**)&P1h,  g_P1h);
    cudaGetSymbolAddress((void**)&P1l,  g_P1l);
    cudaGetSymbolAddress((void**)&P2h,  g_P2h);
    cudaGetSymbolAddress((void**)&P2l,  g_P2l);
    cudaGetSymbolAddress((void**)&P3h,  g_P3h);
    cudaGetSymbolAddress((void**)&P3l,  g_P3l);
    cudaGetSymbolAddress((void**)&P4h,  g_P4h);
    cudaGetSymbolAddress((void**)&P4l,  g_P4l);
    cudaGetSymbolAddress((void**)&Wh,   g_Wh);
    cudaGetSymbolAddress((void**)&Wl,   g_Wl);
    cudaGetSymbolAddress((void**)&cnt,  g_cnt);
    cudaGetSymbolAddress((void**)&dis,  g_dis);
    cudaGetSymbolAddress((void**)&invd, g_invd);
    cudaGetSymbolAddress((void**)&off,  g_off);
    cudaGetSymbolAddress((void**)&cur,  g_cur);
    cudaGetSymbolAddress((void**)&btot, g_btot);
    cudaGetSymbolAddress((void**)&ssrc, g_ssrc);
    cudaGetSymbolAddress((void**)&ssrcp,g_ssrcp);
    cudaGetSymbolAddress((void**)&sw,   g_sw);

    cudaFuncSetAttribute(k_wmma,  cudaFuncAttributeMaxDynamicSharedMemorySize, SMEM_SZ);
    cudaFuncSetAttribute(k_wmmaX, cudaFuncAttributeMaxDynamicSharedMemorySize, SMEM_SZ);

    const int TE  = 256;
    const int GE  = (NE + TE - 1) / TE;
    const int GN  = (NN + TE - 1) / TE;
    const int GW  = (NN * 32 + TE - 1) / TE;
    const int GM  = (NN + 127) / 128;
    const int GM2 = (2 * NN + 127) / 128;
    const int NB  = (NN + SCB - 1) / SCB;
    const size_t HB = (size_t)NN * FD;   // bad-half offset in 2NN buffers

    // ---- prologue (node 5 = k_wmmaX for ncu) ----
    cudaMemsetAsync(cnt, 0, sizeof(int) * 2 * NN);
    k_count<<<GE, TE>>>(ei + NE, cnt);
    k_prepw<<<(512 * 128 + 255) / 256, 256>>>(W1, Wh + WOFF_W1, Wl + WOFF_W1, 512);
    k_deg<<<GN, TE>>>(cnt, dis, invd);
    k_wmmaX<<<GM, 256, SMEM_SZ>>>(x, Wh + WOFF_W1, Wl + WOFF_W1,
                                  nullptr, 0, Hg, nullptr, nullptr, NN, 512);
    k_count<<<GE, TE>>>(eh + NE, cnt + NN);
    k_deg<<<GN, TE>>>(cnt + NN, dis + NN, invd + NN);

    // ---- multi-block scans ----
    k_scan_blk<<<NB, SCB>>>(cnt, off, btot, NN);
    k_scan_tot<<<1, 128>>>(btot, NB, off + NN);
    k_scan_add<<<GN, TE>>>(off, btot, cur, NN);
    k_scan_blk<<<NB, SCB>>>(cnt + NN, off + (NN + 1), btot + 128, NN);
    k_scan_tot<<<1, 128>>>(btot + 128, NB, off + (NN + 1) + NN);
    k_scan_add<<<GN, TE>>>(off + (NN + 1), btot + 128, cur + NN, NN);

    k_place<<<GE, TE>>>(ei, ei + NE, dis,      cur,      ssrc,      sw,
                        perm, ssrcp);
    k_place<<<GE, TE>>>(eh, eh + NE, dis + NN, cur + NN, ssrc + NE, sw + NE,
                        nullptr, nullptr);

    // ---- remaining weight prep ----
    k_prepw<<<(128 * 128 + 255) / 256, 256>>>(W2, Wh + WOFF_W2, Wl + WOFF_W2, 128);
    k_prepw<<<(128 * 128 + 255) / 256, 256>>>(W3, Wh + WOFF_W3, Wl + WOFF_W3, 128);
    k_prepw<<<(128 * 128 + 255) / 256, 256>>>(M1, Wh + WOFF_M1, Wl + WOFF_M1, 128);
    k_prepw<<<(128 * 128 + 255) / 256, 256>>>(M2, Wh + WOFF_M2, Wl + WOFF_M2, 128);
    k_prepw<<<(128 * 128 + 255) / 256, 256>>>(Wd, Wh + WOFF_WD, Wl + WOFF_WD, 128);

    // ---- layer1 aggs back-to-back (Hg stays warm in L2) ----
    k_agg<<<GW, TE>>>(Hg, off, ssrc,  sw, invd, b1, nullptr,
                      nullptr, P1h, P1l, 1);                    // good -> P1[0:NN)
    k_agg<<<GW, TE>>>(Hg, off, ssrcp, sw, invd, b1, perm,
                      nullptr, P1h + HB, P1l + HB, 1);          // bad  -> P1[NN:2NN)

    // ---- batched W2 GEMM over both halves (M = 2*NN) ----
    k_wmma<<<GM2, 256, SMEM_SZ>>>(P1h, P1l, Wh + WOFF_W2, Wl + WOFF_W2,
                                  nullptr, 0, G, nullptr, nullptr, 2 * NN, 128);

    // ---- good half: agg2 (G good-half warm), then consumers of its outputs ----
    k_agg<<<GW, TE>>>(G, off, ssrc, sw, invd, b2, nullptr,
                      EAf, P2h, P2l, 1);
    // M1 immediately (P2 good warm)
    k_wmma<<<GM, 256, SMEM_SZ>>>(P2h, P2l, Wh + WOFF_M1, Wl + WOFF_M1,
                                 mb1, 1, nullptr, P3h, P3l, NN, 128);
    // classifier (EAf still warm-ish)
    k_gemm10<<<GN, TE>>>(EAf, Wc, C10);
    k_agg10<<<GW, TE>>>(C10, off, ssrc, sw, invd, bc, out);
    // rest of T chain
    k_wmma<<<GM, 256, SMEM_SZ>>>(P3h, P3l, Wh + WOFF_M2, Wl + WOFF_M2,
                                 mb2, 0, nullptr, P4h, P4l, NN, 128);
    k_wmma<<<GM, 256, SMEM_SZ>>>(P4h, P4l, Wh + WOFF_WD, Wl + WOFF_WD,
                                 nullptr, 0, T, nullptr, nullptr, NN, 128);
    // W3 good + fused score immediately after (G good-half + T warm)
    k_wmma<<<GM, 256, SMEM_SZ>>>(P2h, P2l, Wh + WOFF_W3, Wl + WOFF_W3,
                                 nullptr, 0, G, nullptr, nullptr, NN, 128);
    k_aggscore<<<GW, TE>>>(G, T, off + (NN + 1), ssrc + NE, sw + NE, invd + NN,
                           b3, out, 10);

    // ---- bad half: agg2 (reads G bad-half), W3, fused score ----
    k_agg<<<GW, TE>>>(G + HB, off, ssrc, sw, invd, b2, nullptr,
                      nullptr, P2h + HB, P2l + HB, 1);
    k_wmma<<<GM, 256, SMEM_SZ>>>(P2h + HB, P2l + HB, Wh + WOFF_W3, Wl + WOFF_W3,
                                 nullptr, 0, G, nullptr, nullptr, NN, 128);
    k_aggscore<<<GW, TE>>>(G, T, off + (NN + 1), ssrc + NE, sw + NE, invd + NN,
                           b3, out, 11);
}

// round 12
// speedup vs baseline: 1.0559x; 1.0559x over previous
#include <cuda_runtime.h>
#include <cuda_bf16.h>
#include <cuda_fp16.h>
#include <math.h>
#include <stdint.h>

#define NN 100000
#define NE 1600000
#define NF 512
#define FD 128
#define NC 10
#define OUTC 12

// ================= PTX helpers (sm_80-compatible only) =================
__device__ __forceinline__ uint32_t s2u(const void* p) {
    uint32_t a;
    asm("{ .reg .u64 t; cvta.to.shared.u64 t, %1; cvt.u32.u64 %0, t; }"
        : "=r"(a) : "l"(p));
    return a;
}
__device__ __forceinline__ void cpa16(uint32_t dst, const void* src) {
    asm volatile("cp.async.cg.shared.global [%0], [%1], 16;" :: "r"(dst), "l"(src));
}
#define CP_COMMIT() asm volatile("cp.async.commit_group;" ::: "memory")
#define CP_WAIT1()  asm volatile("cp.async.wait_group 1;" ::: "memory")
#define CP_WAIT0()  asm volatile("cp.async.wait_group 0;" ::: "memory")

__device__ __forceinline__ void ldsm4(uint32_t* r, uint32_t addr) {
    asm volatile("ldmatrix.sync.aligned.m8n8.x4.shared.b16 {%0,%1,%2,%3}, [%4];"
                 : "=r"(r[0]), "=r"(r[1]), "=r"(r[2]), "=r"(r[3]) : "r"(addr));
}
__device__ __forceinline__ void mma16816(float* c, const uint32_t* a, const uint32_t* b) {
    asm volatile("mma.sync.aligned.m16n8k16.row.col.f32.bf16.bf16.f32 "
                 "{%0,%1,%2,%3}, {%4,%5,%6,%7}, {%8,%9}, {%0,%1,%2,%3};"
                 : "+f"(c[0]), "+f"(c[1]), "+f"(c[2]), "+f"(c[3])
                 : "r"(a[0]), "r"(a[1]), "r"(a[2]), "r"(a[3]), "r"(b[0]), "r"(b[1]));
}

// ================= scratch (device globals) =================
// Gather operands stored fp16 (halves agg L2 traffic). 2NN halves: good/bad.
__device__ __half g_Hh [(size_t)NN * FD];
__device__ __half g_Gh [(size_t)2 * NN * FD];
__device__ float g_EAf[(size_t)NN * FD];
__device__ float g_T  [(size_t)NN * FD];
__device__ float g_C10[(size_t)NN * NC];
__device__ __nv_bfloat16 g_P1h[(size_t)2 * NN * FD];
__device__ __nv_bfloat16 g_P1l[(size_t)2 * NN * FD];
__device__ __nv_bfloat16 g_P2h[(size_t)2 * NN * FD];
__device__ __nv_bfloat16 g_P2l[(size_t)2 * NN * FD];
__device__ __nv_bfloat16 g_P3h[(size_t)NN * FD];
__device__ __nv_bfloat16 g_P3l[(size_t)NN * FD];
__device__ __nv_bfloat16 g_P4h[(size_t)NN * FD];
__device__ __nv_bfloat16 g_P4l[(size_t)NN * FD];
#define WOFF_W1 0
#define WOFF_W2 (128 * 512)
#define WOFF_W3 (WOFF_W2 + 128 * 128)
#define WOFF_M1 (WOFF_W3 + 128 * 128)
#define WOFF_M2 (WOFF_M1 + 128 * 128)
#define WOFF_WD (WOFF_M2 + 128 * 128)
#define WTOT    (WOFF_WD + 128 * 128)
__device__ __nv_bfloat16 g_Wh[WTOT];
__device__ __nv_bfloat16 g_Wl[WTOT];
__device__ int   g_cnt [2 * NN];
__device__ float g_dis [2 * NN];
__device__ float g_invd[2 * NN];
__device__ int   g_off [2 * (NN + 1)];
__device__ int   g_cur [2 * NN];
__device__ int   g_btot[2 * 128];
__device__ int   g_ssrc[2 * NE];
__device__ int   g_ssrcp[NE];
__device__ float g_sw  [2 * NE];

// ================= CSR build =================
__global__ void k_count(const int* __restrict__ dst, int* __restrict__ cnt) {
    int i = blockIdx.x * blockDim.x + threadIdx.x;
    if (i < NE) atomicAdd(&cnt[dst[i]], 1);
}

__global__ void k_deg(const int* __restrict__ cnt, float* __restrict__ dis,
                      float* __restrict__ invd) {
    int i = blockIdx.x * blockDim.x + threadIdx.x;
    if (i < NN) {
        float d = (float)(cnt[i] + 1);
        dis[i]  = rsqrtf(d);
        invd[i] = 1.0f / d;
    }
}

// ---- multi-block scan ----
#define SCB 1024
__global__ void k_scan_blk(const int* __restrict__ cnt, int* __restrict__ off,
                           int* __restrict__ btot, int n) {
    __shared__ int ws[32];
    const unsigned FULL = 0xffffffffu;
    int t = threadIdx.x, w = t >> 5, l = t & 31;
    int i = blockIdx.x * SCB + t;
    int v = (i < n) ? cnt[i] : 0;
    int s = v;
    #pragma unroll
    for (int d = 1; d < 32; d <<= 1) {
        int o = __shfl_up_sync(FULL, s, d);
        if (l >= d) s += o;
    }
    if (l == 31) ws[w] = s;
    __syncthreads();
    if (w == 0) {
        int x2 = ws[l];
        #pragma unroll
        for (int d = 1; d < 32; d <<= 1) {
            int o = __shfl_up_sync(FULL, x2, d);
            if (l >= d) x2 += o;
        }
        ws[l] = x2;
    }
    __syncthreads();
    int incl = s + (w > 0 ? ws[w - 1] : 0);
    if (i < n) off[i] = incl - v;
    if (t == SCB - 1) btot[blockIdx.x] = incl;
}

__global__ void k_scan_tot(int* __restrict__ btot, int nb, int* __restrict__ offN) {
    __shared__ int sh[128];
    int t = threadIdx.x;
    int v = (t < nb) ? btot[t] : 0;
    sh[t] = v;
    __syncthreads();
    #pragma unroll
    for (int d = 1; d < 128; d <<= 1) {
        int o = (t >= d) ? sh[t - d] : 0;
        __syncthreads();
        sh[t] += o;
        __syncthreads();
    }
    if (t < nb) btot[t] = sh[t] - v;
    if (t == 127) *offN = sh[127];
}

__global__ void k_scan_add(int* __restrict__ off, const int* __restrict__ btot,
                           int* __restrict__ cur, int n) {
    int i = blockIdx.x * blockDim.x + threadIdx.x;
    if (i < n) {
        int e = off[i] + btot[i >> 10];
        off[i] = e;
        cur[i] = e;
    }
}

__global__ void k_place(const int* __restrict__ src, const int* __restrict__ dst,
                        const float* __restrict__ dis, int* __restrict__ cur,
                        int* __restrict__ ssrc, float* __restrict__ sw,
                        const int* __restrict__ perm, int* __restrict__ ssrcp) {
    int e = blockIdx.x * blockDim.x + threadIdx.x;
    if (e < NE) {
        int s = src[e], d = dst[e];
        int p = atomicAdd(&cur[d], 1);
        ssrc[p] = s;
        sw[p]   = dis[s] * dis[d];
        if (ssrcp) ssrcp[p] = perm[s];
    }
}

// ================= weight prep =================
__global__ void k_prepw(const float* __restrict__ W, __nv_bfloat16* __restrict__ Bh,
                        __nv_bfloat16* __restrict__ Bl, int K) {
    int i = blockIdx.x * blockDim.x + threadIdx.x;
    if (i < K * 128) {
        int n = i / K, k = i - n * K;
        float v = W[(size_t)k * 128 + n];
        __nv_bfloat16 h = __float2bfloat16(v);
        Bh[(size_t)n * K + k] = h;
        Bl[(size_t)n * K + k] = __float2bfloat16(v - __bfloat162float(h));
    }
}

// ================= mma.sync split-bf16 GEMM =================
#define STRIDE_B 80
#define ARR_SZ   (128 * STRIDE_B)
#define STAGE_SZ (4 * ARR_SZ)
#define SMEM_SZ  (2 * STAGE_SZ)

__device__ __forceinline__ void wmma_prefetch(
    uint32_t sbase, const __nv_bfloat16* Ah, const __nv_bfloat16* Al,
    const __nv_bfloat16* Bh, const __nv_bfloat16* Bl,
    int m0, int M, int K, int k0, int tid)
{
    #pragma unroll
    for (int p = 0; p < 2; p++) {
        int idx = tid + p * 256;
        int row = idx >> 2, cg = idx & 3;
        int gr = m0 + row; if (gr >= M) gr = M - 1;
        size_t aoff = (size_t)gr * K + k0 + cg * 8;
        size_t boff = (size_t)row * K + k0 + cg * 8;
        uint32_t so = row * STRIDE_B + cg * 16;
        cpa16(sbase + 0 * ARR_SZ + so, Ah + aoff);
        cpa16(sbase + 1 * ARR_SZ + so, Al + aoff);
        cpa16(sbase + 2 * ARR_SZ + so, Bh + boff);
        cpa16(sbase + 3 * ARR_SZ + so, Bl + boff);
    }
}

#define WMMA_MAINLOOP_BODY(st)                                                   \
    {                                                                            \
        _Pragma("unroll")                                                        \
        for (int kk = 0; kk < 2; kk++) {                                         \
            const uint32_t kb = kk * 32;                                         \
            uint32_t ah[2][4], al[2][4], bh[4][4], bl[4][4];                     \
            _Pragma("unroll")                                                    \
            for (int mt = 0; mt < 2; mt++) {                                     \
                uint32_t ao = (st) + aoffs + mt * (16 * STRIDE_B) + kb;          \
                ldsm4(ah[mt], ao + 0 * ARR_SZ);                                  \
                ldsm4(al[mt], ao + 1 * ARR_SZ);                                  \
            }                                                                    \
            _Pragma("unroll")                                                    \
            for (int np = 0; np < 4; np++) {                                     \
                uint32_t bo = (st) + boffs + np * (16 * STRIDE_B) + kb;          \
                ldsm4(bh[np], bo + 2 * ARR_SZ);                                  \
                ldsm4(bl[np], bo + 3 * ARR_SZ);                                  \
            }                                                                    \
            _Pragma("unroll")                                                    \
            for (int mt = 0; mt < 2; mt++)                                       \
                _Pragma("unroll")                                                \
                for (int nt = 0; nt < 8; nt++) {                                 \
                    float* cc = c[mt][nt];                                       \
                    const uint32_t* ph = &bh[nt >> 1][(nt & 1) * 2];             \
                    const uint32_t* pl = &bl[nt >> 1][(nt & 1) * 2];             \
                    mma16816(cc, ah[mt], ph);                                    \
                    mma16816(cc, ah[mt], pl);                                    \
                    mma16816(cc, al[mt], ph);                                    \
                }                                                                \
        }                                                                        \
    }

// Epilogue: optional f32 / fp16 / split-bf16 outputs
#define WMMA_EPILOGUE()                                                          \
    _Pragma("unroll")                                                            \
    for (int mt = 0; mt < 2; mt++) {                                             \
        _Pragma("unroll")                                                        \
        for (int part = 0; part < 2; part++) {                                   \
            int gr = m0 + wm0 + mt * 16 + (lane >> 2) + part * 8;                \
            if (gr >= M) continue;                                               \
            _Pragma("unroll")                                                    \
            for (int nt = 0; nt < 8; nt++) {                                     \
                int gcol = wn0 + nt * 8 + (lane & 3) * 2;                        \
                float v0 = c[mt][nt][part * 2 + 0];                              \
                float v1 = c[mt][nt][part * 2 + 1];                              \
                if (bias) { v0 += bias[gcol]; v1 += bias[gcol + 1]; }            \
                if (dorelu) { v0 = fmaxf(v0, 0.f); v1 = fmaxf(v1, 0.f); }        \
                if (Cf)                                                          \
                    *(float2*)(Cf + (size_t)gr * FD + gcol) = make_float2(v0, v1); \
                if (Chf) {                                                       \
                    __half2 hh = __floats2half2_rn(v0, v1);                      \
                    *(uint32_t*)(Chf + (size_t)gr * FD + gcol) = *(uint32_t*)&hh; \
                }                                                                \
                if (Chi) {                                                       \
                    __nv_bfloat16 h0 = __float2bfloat16(v0);                     \
                    __nv_bfloat16 h1 = __float2bfloat16(v1);                     \
                    __nv_bfloat162 hp = __halves2bfloat162(h0, h1);              \
                    __nv_bfloat162 lp = __halves2bfloat162(                      \
                        __float2bfloat16(v0 - __bfloat162float(h0)),             \
                        __float2bfloat16(v1 - __bfloat162float(h1)));            \
                    *(uint32_t*)(Chi + (size_t)gr * FD + gcol) = *(uint32_t*)&hp; \
                    *(uint32_t*)(Clo + (size_t)gr * FD + gcol) = *(uint32_t*)&lp; \
                }                                                                \
            }                                                                    \
        }                                                                        \
    }

__global__ void __launch_bounds__(256, 2) k_wmma(
    const __nv_bfloat16* __restrict__ Ahi, const __nv_bfloat16* __restrict__ Alo,
    const __nv_bfloat16* __restrict__ Bhi, const __nv_bfloat16* __restrict__ Blo,
    const float* __restrict__ bias, int dorelu,
    float* __restrict__ Cf, __half* __restrict__ Chf,
    __nv_bfloat16* __restrict__ Chi, __nv_bfloat16* __restrict__ Clo, int M, int K)
{
    extern __shared__ char smem[];
    const uint32_t sb = s2u(smem);
    const int tid  = threadIdx.x;
    const int lane = tid & 31, w = tid >> 5;
    const int wm0 = (w >> 1) * 32, wn0 = (w & 1) * 64;
    const int m0  = blockIdx.x * 128;

    float c[2][8][4];
    #pragma unroll
    for (int i = 0; i < 2; i++)
        #pragma unroll
        for (int j = 0; j < 8; j++)
            #pragma unroll
            for (int q = 0; q < 4; q++) c[i][j][q] = 0.f;

    const uint32_t aoffs = (uint32_t)((wm0 + (lane & 15)) * STRIDE_B + (lane >> 4) * 16);
    const uint32_t boffs = (uint32_t)((wn0 + ((lane >> 4) & 1) * 8 + (lane & 7)) * STRIDE_B
                                      + ((lane >> 3) & 1) * 16);

    const int nch = K >> 5;
    wmma_prefetch(sb, Ahi, Alo, Bhi, Blo, m0, M, K, 0, tid);
    CP_COMMIT();

    for (int ch = 0; ch < nch; ch++) {
        if (ch + 1 < nch) {
            wmma_prefetch(sb + ((ch + 1) & 1) * STAGE_SZ, Ahi, Alo, Bhi, Blo,
                          m0, M, K, (ch + 1) << 5, tid);
            CP_COMMIT();
            CP_WAIT1();
        } else {
            CP_WAIT0();
        }
        __syncthreads();
        const uint32_t st = sb + (ch & 1) * STAGE_SZ;
        WMMA_MAINLOOP_BODY(st)
        __syncthreads();
    }
    WMMA_EPILOGUE()
}

// ---- variant: A is f32, split to hi/lo on the fly (for x @ W1) ----
__global__ void __launch_bounds__(256, 2) k_wmmaX(
    const float* __restrict__ Af,
    const __nv_bfloat16* __restrict__ Bhi, const __nv_bfloat16* __restrict__ Blo,
    const float* __restrict__ bias, int dorelu,
    float* __restrict__ Cf, __half* __restrict__ Chf,
    __nv_bfloat16* __restrict__ Chi, __nv_bfloat16* __restrict__ Clo, int M, int K)
{
    extern __shared__ char smem[];
    const uint32_t sb = s2u(smem);
    const int tid  = threadIdx.x;
    const int lane = tid & 31, w = tid >> 5;
    const int wm0 = (w >> 1) * 32, wn0 = (w & 1) * 64;
    const int m0  = blockIdx.x * 128;

    float c[2][8][4];
    #pragma unroll
    for (int i = 0; i < 2; i++)
        #pragma unroll
        for (int j = 0; j < 8; j++)
            #pragma unroll
            for (int q = 0; q < 4; q++) c[i][j][q] = 0.f;

    const uint32_t aoffs = (uint32_t)((wm0 + (lane & 15)) * STRIDE_B + (lane >> 4) * 16);
    const uint32_t boffs = (uint32_t)((wn0 + ((lane >> 4) & 1) * 8 + (lane & 7)) * STRIDE_B
                                      + ((lane >> 3) & 1) * 16);

    const int nch = K >> 5;

    #define PREFETCH_X(sbase, k0)                                                 \
    {                                                                             \
        _Pragma("unroll")                                                         \
        for (int p = 0; p < 2; p++) {                                             \
            int idx = tid + p * 256;                                              \
            int row = idx >> 2, cg = idx & 3;                                     \
            int gr = m0 + row; if (gr >= M) gr = M - 1;                           \
            size_t aoff = (size_t)gr * K + (k0) + cg * 8;                         \
            size_t boff = (size_t)row * K + (k0) + cg * 8;                        \
            uint32_t so = row * STRIDE_B + cg * 16;                               \
            cpa16((sbase) + 2 * ARR_SZ + so, Bhi + boff);                         \
            cpa16((sbase) + 3 * ARR_SZ + so, Blo + boff);                         \
            float4 v0 = *(const float4*)(Af + aoff);                              \
            float4 v1 = *(const float4*)(Af + aoff + 4);                          \
            float vv[8] = {v0.x, v0.y, v0.z, v0.w, v1.x, v1.y, v1.z, v1.w};       \
            uint32_t hw[4], lw[4];                                                \
            _Pragma("unroll")                                                     \
            for (int q = 0; q < 4; q++) {                                         \
                __nv_bfloat16 h0 = __float2bfloat16(vv[2 * q]);                   \
                __nv_bfloat16 h1 = __float2bfloat16(vv[2 * q + 1]);               \
                __nv_bfloat162 hp = __halves2bfloat162(h0, h1);                   \
                __nv_bfloat162 lp = __halves2bfloat162(                           \
                    __float2bfloat16(vv[2 * q] - __bfloat162float(h0)),           \
                    __float2bfloat16(vv[2 * q + 1] - __bfloat162float(h1)));      \
                hw[q] = *(uint32_t*)&hp;                                          \
                lw[q] = *(uint32_t*)&lp;                                          \
            }                                                                     \
            asm volatile("st.shared.v4.b32 [%0], {%1,%2,%3,%4};"                  \
                :: "r"((sbase) + 0 * ARR_SZ + so),                                \
                   "r"(hw[0]), "r"(hw[1]), "r"(hw[2]), "r"(hw[3]) : "memory");    \
            asm volatile("st.shared.v4.b32 [%0], {%1,%2,%3,%4};"                  \
                :: "r"((sbase) + 1 * ARR_SZ + so),                                \
                   "r"(lw[0]), "r"(lw[1]), "r"(lw[2]), "r"(lw[3]) : "memory");    \
        }                                                                         \
    }

    PREFETCH_X(sb, 0)
    CP_COMMIT();

    for (int ch = 0; ch < nch; ch++) {
        if (ch + 1 < nch) {
            PREFETCH_X(sb + ((ch + 1) & 1) * STAGE_SZ, (ch + 1) << 5)
            CP_COMMIT();
            CP_WAIT1();
        } else {
            CP_WAIT0();
        }
        __syncthreads();
        const uint32_t st = sb + (ch & 1) * STAGE_SZ;
        WMMA_MAINLOOP_BODY(st)
        __syncthreads();
    }
    WMMA_EPILOGUE()
    #undef PREFETCH_X
}

// ======== gather aggregation (fp16 input rows, fp32 accumulate) ========
__global__ void k_agg(const __half* __restrict__ h, const int* __restrict__ off,
                      const int* __restrict__ ssrc, const float* __restrict__ sw,
                      const float* __restrict__ invd, const float* __restrict__ bias,
                      const int* __restrict__ selfmap,
                      float* __restrict__ outf, __nv_bfloat16* __restrict__ outhi,
                      __nv_bfloat16* __restrict__ outlo, int dorelu)
{
    int node = (blockIdx.x * blockDim.x + threadIdx.x) >> 5;
    int lane = threadIdx.x & 31;
    if (node >= NN) return;
    int s = off[node], e = off[node + 1];
    float4 acc = make_float4(0.f, 0.f, 0.f, 0.f);
    for (int i = s; i < e; i++) {
        int   src = ssrc[i];
        float w   = sw[i];
        uint2 raw = *(const uint2*)(h + (size_t)src * FD + lane * 4);
        float2 f0 = __half22float2(*(__half2*)&raw.x);
        float2 f1 = __half22float2(*(__half2*)&raw.y);
        acc.x = fmaf(w, f0.x, acc.x);
        acc.y = fmaf(w, f0.y, acc.y);
        acc.z = fmaf(w, f1.x, acc.z);
        acc.w = fmaf(w, f1.y, acc.w);
    }
    int self = selfmap ? selfmap[node] : node;
    float id = invd[node];
    uint2 rs = *(const uint2*)(h + (size_t)self * FD + lane * 4);
    float2 s0 = __half22float2(*(__half2*)&rs.x);
    float2 s1 = __half22float2(*(__half2*)&rs.y);
    float4 b = *(const float4*)(bias + lane * 4);
    acc.x = fmaf(id, s0.x, acc.x) + b.x;
    acc.y = fmaf(id, s0.y, acc.y) + b.y;
    acc.z = fmaf(id, s1.x, acc.z) + b.z;
    acc.w = fmaf(id, s1.y, acc.w) + b.w;
    if (dorelu) {
        acc.x = fmaxf(acc.x, 0.f); acc.y = fmaxf(acc.y, 0.f);
        acc.z = fmaxf(acc.z, 0.f); acc.w = fmaxf(acc.w, 0.f);
    }
    if (outf)
        *(float4*)(outf + (size_t)node * FD + lane * 4) = acc;
    if (outhi) {
        float vv[4] = {acc.x, acc.y, acc.z, acc.w};
        uint32_t hw[2], lw[2];
        #pragma unroll
        for (int q = 0; q < 2; q++) {
            __nv_bfloat16 ha = __float2bfloat16(vv[2 * q]);
            __nv_bfloat16 hb = __float2bfloat16(vv[2 * q + 1]);
            __nv_bfloat162 hp = __halves2bfloat162(ha, hb);
            __nv_bfloat162 lp = __halves2bfloat162(
                __float2bfloat16(vv[2 * q] - __bfloat162float(ha)),
                __float2bfloat16(vv[2 * q + 1] - __bfloat162float(hb)));
            hw[q] = *(uint32_t*)&hp;
            lw[q] = *(uint32_t*)&lp;
        }
        *(uint2*)(outhi + (size_t)node * FD + lane * 4) = make_uint2(hw[0], hw[1]);
        *(uint2*)(outlo + (size_t)node * FD + lane * 4) = make_uint2(lw[0], lw[1]);
    }
}

// ===== fused hop-agg + bilinear score (fp16 G rows) =====
__global__ void k_aggscore(const __half* __restrict__ G, const float* __restrict__ T,
                           const int* __restrict__ off, const int* __restrict__ ssrc,
                           const float* __restrict__ sw, const float* __restrict__ invd,
                           const float* __restrict__ b3, float* __restrict__ out,
                           int col)
{
    const unsigned FULL = 0xffffffffu;
    int node = (blockIdx.x * blockDim.x + threadIdx.x) >> 5;
    int lane = threadIdx.x & 31;
    if (node >= NN) return;
    float4 tv = *(const float4*)(T + (size_t)node * FD + lane * 4);
    int s = off[node], e = off[node + 1];
    float acc = 0.f;
    for (int i = s; i < e; i++) {
        int   src = ssrc[i];
        float w   = sw[i];
        uint2 raw = *(const uint2*)(G + (size_t)src * FD + lane * 4);
        float2 f0 = __half22float2(*(__half2*)&raw.x);
        float2 f1 = __half22float2(*(__half2*)&raw.y);
        acc = fmaf(w, tv.x * f0.x + tv.y * f0.y + tv.z * f1.x + tv.w * f1.y, acc);
    }
    uint2 rs = *(const uint2*)(G + (size_t)node * FD + lane * 4);
    float2 s0 = __half22float2(*(__half2*)&rs.x);
    float2 s1 = __half22float2(*(__half2*)&rs.y);
    float4 bb = *(const float4*)(b3 + lane * 4);
    acc = fmaf(invd[node], tv.x * s0.x + tv.y * s0.y + tv.z * s1.x + tv.w * s1.y, acc);
    acc += tv.x * bb.x + tv.y * bb.y + tv.z * bb.z + tv.w * bb.w;
    #pragma unroll
    for (int d = 16; d > 0; d >>= 1) acc += __shfl_xor_sync(FULL, acc, d);
    if (lane == 0)
        out[(size_t)node * OUTC + col] = 1.0f / (1.0f + expf(-acc));
}

// ================= classifier =================
__global__ void k_gemm10(const float* __restrict__ A, const float* __restrict__ W,
                         float* __restrict__ C)
{
    __shared__ float w[FD * NC];
    for (int i = threadIdx.x; i < FD * NC; i += blockDim.x) w[i] = W[i];
    __syncthreads();
    int r = blockIdx.x * blockDim.x + threadIdx.x;
    if (r >= NN) return;
    float acc[NC];
    #pragma unroll
    for (int j = 0; j < NC; j++) acc[j] = 0.f;
    const float4* ap = (const float4*)(A + (size_t)r * FD);
    #pragma unroll 8
    for (int k4 = 0; k4 < 32; k4++) {
        float4 v = ap[k4];
        int k = k4 * 4;
        #pragma unroll
        for (int j = 0; j < NC; j++) {
            acc[j] = fmaf(v.x, w[(k + 0) * NC + j], acc[j]);
            acc[j] = fmaf(v.y, w[(k + 1) * NC + j], acc[j]);
            acc[j] = fmaf(v.z, w[(k + 2) * NC + j], acc[j]);
            acc[j] = fmaf(v.w, w[(k + 3) * NC + j], acc[j]);
        }
    }
    #pragma unroll
    for (int j = 0; j < NC; j++) C[(size_t)r * NC + j] = acc[j];
}

__global__ void k_agg10(const float* __restrict__ h, const int* __restrict__ off,
                        const int* __restrict__ ssrc, const float* __restrict__ sw,
                        const float* __restrict__ invd, const float* __restrict__ bc,
                        float* __restrict__ out)
{
    int node = (blockIdx.x * blockDim.x + threadIdx.x) >> 5;
    int lane = threadIdx.x & 31;
    if (node >= NN || lane >= NC) return;
    int s = off[node], e = off[node + 1];
    float acc = 0.f;
    for (int i = s; i < e; i++) {
        int src = ssrc[i];
        acc = fmaf(sw[i], h[(size_t)src * NC + lane], acc);
    }
    acc = fmaf(invd[node], h[(size_t)node * NC + lane], acc) + bc[lane];
    out[(size_t)node * OUTC + lane] = acc;
}

// ================= host =================
extern "C" void kernel_launch(void* const* d_in, const int* in_sizes, int n_in,
                              void* d_out, int out_size)
{
    const float* x    = (const float*)d_in[0];
    const int*   ei   = (const int*)  d_in[1];
    const int*   eh   = (const int*)  d_in[2];
    const int*   perm = (const int*)  d_in[4];
    const float* W1   = (const float*)d_in[5];
    const float* b1   = (const float*)d_in[6];
    const float* W2   = (const float*)d_in[7];
    const float* b2   = (const float*)d_in[8];
    const float* W3   = (const float*)d_in[9];
    const float* b3   = (const float*)d_in[10];
    const float* M1   = (const float*)d_in[11];
    const float* mb1  = (const float*)d_in[12];
    const float* M2   = (const float*)d_in[13];
    const float* mb2  = (const float*)d_in[14];
    const float* Wc   = (const float*)d_in[15];
    const float* bc   = (const float*)d_in[16];
    const float* Wd   = (const float*)d_in[17];
    float* out = (float*)d_out;

    float *EAf, *T, *C10, *dis, *invd, *sw;
    __half *Hh, *Gh;
    __nv_bfloat16 *P1h, *P1l, *P2h, *P2l, *P3h, *P3l, *P4h, *P4l, *Wh, *Wl;
    int *cnt, *off, *cur, *btot, *ssrc, *ssrcp;
    cudaGetSymbolAddress((void**)&Hh,   g_Hh);
    cudaGetSymbolAddress((void**)&Gh,   g_Gh);
    cudaGetSymbolAddress((void**)&EAf,  g_EAf);
    cudaGetSymbolAddress((void**)&T,    g_T);
    cudaGetSymbolAddress((void**)&C10,  g_C10);
    cudaGetSymbolAddress((void**)&P1h,  g_P1h);
    cudaGetSymbolAddress((void**)&P1l,  g_P1l);
    cudaGetSymbolAddress((void**)&P2h,  g_P2h);
    cudaGetSymbolAddress((void**)&P2l,  g_P2l);
    cudaGetSymbolAddress((void**)&P3h,  g_P3h);
    cudaGetSymbolAddress((void**)&P3l,  g_P3l);
    cudaGetSymbolAddress((void**)&P4h,  g_P4h);
    cudaGetSymbolAddress((void**)&P4l,  g_P4l);
    cudaGetSymbolAddress((void**)&Wh,   g_Wh);
    cudaGetSymbolAddress((void**)&Wl,   g_Wl);
    cudaGetSymbolAddress((void**)&cnt,  g_cnt);
    cudaGetSymbolAddress((void**)&dis,  g_dis);
    cudaGetSymbolAddress((void**)&invd, g_invd);
    cudaGetSymbolAddress((void**)&off,  g_off);
    cudaGetSymbolAddress((void**)&cur,  g_cur);
    cudaGetSymbolAddress((void**)&btot, g_btot);
    cudaGetSymbolAddress((void**)&ssrc, g_ssrc);
    cudaGetSymbolAddress((void**)&ssrcp,g_ssrcp);
    cudaGetSymbolAddress((void**)&sw,   g_sw);

    cudaFuncSetAttribute(k_wmma,  cudaFuncAttributeMaxDynamicSharedMemorySize, SMEM_SZ);
    cudaFuncSetAttribute(k_wmmaX, cudaFuncAttributeMaxDynamicSharedMemorySize, SMEM_SZ);

    const int TE  = 256;
    const int GE  = (NE + TE - 1) / TE;
    const int GN  = (NN + TE - 1) / TE;
    const int GW  = (NN * 32 + TE - 1) / TE;
    const int GM  = (NN + 127) / 128;
    const int GM2 = (2 * NN + 127) / 128;
    const int NB  = (NN + SCB - 1) / SCB;
    const size_t HB = (size_t)NN * FD;

    // ---- prologue (node 5 = k_wmmaX for ncu) ----
    cudaMemsetAsync(cnt, 0, sizeof(int) * 2 * NN);
    k_count<<<GE, TE>>>(ei + NE, cnt);
    k_prepw<<<(512 * 128 + 255) / 256, 256>>>(W1, Wh + WOFF_W1, Wl + WOFF_W1, 512);
    k_deg<<<GN, TE>>>(cnt, dis, invd);
    k_wmmaX<<<GM, 256, SMEM_SZ>>>(x, Wh + WOFF_W1, Wl + WOFF_W1,
                                  nullptr, 0, nullptr, Hh, nullptr, nullptr, NN, 512);
    k_count<<<GE, TE>>>(eh + NE, cnt + NN);
    k_deg<<<GN, TE>>>(cnt + NN, dis + NN, invd + NN);

    // ---- multi-block scans ----
    k_scan_blk<<<NB, SCB>>>(cnt, off, btot, NN);
    k_scan_tot<<<1, 128>>>(btot, NB, off + NN);
    k_scan_add<<<GN, TE>>>(off, btot, cur, NN);
    k_scan_blk<<<NB, SCB>>>(cnt + NN, off + (NN + 1), btot + 128, NN);
    k_scan_tot<<<1, 128>>>(btot + 128, NB, off + (NN + 1) + NN);
    k_scan_add<<<GN, TE>>>(off + (NN + 1), btot + 128, cur + NN, NN);

    k_place<<<GE, TE>>>(ei, ei + NE, dis,      cur,      ssrc,      sw,
                        perm, ssrcp);
    k_place<<<GE, TE>>>(eh, eh + NE, dis + NN, cur + NN, ssrc + NE, sw + NE,
                        nullptr, nullptr);

    // ---- remaining weight prep ----
    k_prepw<<<(128 * 128 + 255) / 256, 256>>>(W2, Wh + WOFF_W2, Wl + WOFF_W2, 128);
    k_prepw<<<(128 * 128 + 255) / 256, 256>>>(W3, Wh + WOFF_W3, Wl + WOFF_W3, 128);
    k_prepw<<<(128 * 128 + 255) / 256, 256>>>(M1, Wh + WOFF_M1, Wl + WOFF_M1, 128);
    k_prepw<<<(128 * 128 + 255) / 256, 256>>>(M2, Wh + WOFF_M2, Wl + WOFF_M2, 128);
    k_prepw<<<(128 * 128 + 255) / 256, 256>>>(Wd, Wh + WOFF_WD, Wl + WOFF_WD, 128);

    // ---- layer1 aggs back-to-back (Hh warm in L2, now only 25.6 MB) ----
    k_agg<<<GW, TE>>>(Hh, off, ssrc,  sw, invd, b1, nullptr,
                      nullptr, P1h, P1l, 1);
    k_agg<<<GW, TE>>>(Hh, off, ssrcp, sw, invd, b1, perm,
                      nullptr, P1h + HB, P1l + HB, 1);

    // ---- batched W2 GEMM over both halves -> Gh (fp16) ----
    k_wmma<<<GM2, 256, SMEM_SZ>>>(P1h, P1l, Wh + WOFF_W2, Wl + WOFF_W2,
                                  nullptr, 0, nullptr, Gh, nullptr, nullptr,
                                  2 * NN, 128);

    // ---- good half ----
    k_agg<<<GW, TE>>>(Gh, off, ssrc, sw, invd, b2, nullptr,
                      EAf, P2h, P2l, 1);
    k_wmma<<<GM, 256, SMEM_SZ>>>(P2h, P2l, Wh + WOFF_M1, Wl + WOFF_M1,
                                 mb1, 1, nullptr, nullptr, P3h, P3l, NN, 128);
    k_gemm10<<<GN, TE>>>(EAf, Wc, C10);
    k_agg10<<<GW, TE>>>(C10, off, ssrc, sw, invd, bc, out);
    k_wmma<<<GM, 256, SMEM_SZ>>>(P3h, P3l, Wh + WOFF_M2, Wl + WOFF_M2,
                                 mb2, 0, nullptr, nullptr, P4h, P4l, NN, 128);
    k_wmma<<<GM, 256, SMEM_SZ>>>(P4h, P4l, Wh + WOFF_WD, Wl + WOFF_WD,
                                 nullptr, 0, T, nullptr, nullptr, nullptr, NN, 128);
    // W3 good -> Gh (good half), fused score
    k_wmma<<<GM, 256, SMEM_SZ>>>(P2h, P2l, Wh + WOFF_W3, Wl + WOFF_W3,
                                 nullptr, 0, nullptr, Gh, nullptr, nullptr, NN, 128);
    k_aggscore<<<GW, TE>>>(Gh, T, off + (NN + 1), ssrc + NE, sw + NE, invd + NN,
                           b3, out, 10);

    // ---- bad half ----
    k_agg<<<GW, TE>>>(Gh + HB, off, ssrc, sw, invd, b2, nullptr,
                      nullptr, P2h + HB, P2l + HB, 1);
    k_wmma<<<GM, 256, SMEM_SZ>>>(P2h + HB, P2l + HB, Wh + WOFF_W3, Wl + WOFF_W3,
                                 nullptr, 0, nullptr, Gh, nullptr, nullptr, NN, 128);
    k_aggscore<<<GW, TE>>>(Gh, T, off + (NN + 1), ssrc + NE, sw + NE, invd + NN,
                           b3, out, 11);
}

// round 13
// speedup vs baseline: 1.3115x; 1.2421x over previous
#include <cuda_runtime.h>
#include <cuda_bf16.h>
#include <cuda_fp16.h>
#include <math.h>
#include <stdint.h>

#define NN 100000
#define NE 1600000
#define NF 512
#define FD 128
#define NC 10
#define OUTC 12

// ================= PTX helpers (sm_80-compatible only) =================
__device__ __forceinline__ uint32_t s2u(const void* p) {
    uint32_t a;
    asm("{ .reg .u64 t; cvta.to.shared.u64 t, %1; cvt.u32.u64 %0, t; }"
        : "=r"(a) : "l"(p));
    return a;
}
__device__ __forceinline__ void cpa16(uint32_t dst, const void* src) {
    asm volatile("cp.async.cg.shared.global [%0], [%1], 16;" :: "r"(dst), "l"(src));
}
#define CP_COMMIT() asm volatile("cp.async.commit_group;" ::: "memory")
#define CP_WAIT1()  asm volatile("cp.async.wait_group 1;" ::: "memory")
#define CP_WAIT0()  asm volatile("cp.async.wait_group 0;" ::: "memory")

__device__ __forceinline__ void ldsm4(uint32_t* r, uint32_t addr) {
    asm volatile("ldmatrix.sync.aligned.m8n8.x4.shared.b16 {%0,%1,%2,%3}, [%4];"
                 : "=r"(r[0]), "=r"(r[1]), "=r"(r[2]), "=r"(r[3]) : "r"(addr));
}
__device__ __forceinline__ void mma16816h(float* c, const uint32_t* a, const uint32_t* b) {
    asm volatile("mma.sync.aligned.m16n8k16.row.col.f32.f16.f16.f32 "
                 "{%0,%1,%2,%3}, {%4,%5,%6,%7}, {%8,%9}, {%0,%1,%2,%3};"
                 : "+f"(c[0]), "+f"(c[1]), "+f"(c[2]), "+f"(c[3])
                 : "r"(a[0]), "r"(a[1]), "r"(a[2]), "r"(a[3]), "r"(b[0]), "r"(b[1]));
}

// ================= scratch (device globals) =================
// All activations fp16. 2NN buffers: [0,NN)=good, [NN,2NN)=bad.
__device__ __half g_Hh [(size_t)NN * FD];
__device__ __half g_P1 [(size_t)2 * NN * FD];
__device__ __half g_Gh [(size_t)2 * NN * FD];
__device__ __half g_P2 [(size_t)2 * NN * FD];
__device__ __half g_P3 [(size_t)NN * FD];
__device__ __half g_P4 [(size_t)NN * FD];
__device__ float g_EAf[(size_t)NN * FD];
__device__ float g_T  [(size_t)NN * FD];
__device__ float g_C10[(size_t)NN * NC];
#define WOFF_W1 0
#define WOFF_W2 (128 * 512)
#define WOFF_W3 (WOFF_W2 + 128 * 128)
#define WOFF_M1 (WOFF_W3 + 128 * 128)
#define WOFF_M2 (WOFF_M1 + 128 * 128)
#define WOFF_WD (WOFF_M2 + 128 * 128)
#define WTOT    (WOFF_WD + 128 * 128)
__device__ __half g_Wf[WTOT];
__device__ int   g_cnt [2 * NN];
__device__ float g_dis [2 * NN];
__device__ float g_invd[2 * NN];
__device__ int   g_off [2 * (NN + 1)];
__device__ int   g_cur [2 * NN];
__device__ int   g_btot[2 * 128];
__device__ int   g_ssrc[2 * NE];
__device__ int   g_ssrcp[NE];
__device__ float g_sw  [2 * NE];

// ================= CSR build =================
__global__ void k_count(const int* __restrict__ dst, int* __restrict__ cnt) {
    int i = blockIdx.x * blockDim.x + threadIdx.x;
    if (i < NE) atomicAdd(&cnt[dst[i]], 1);
}

__global__ void k_deg(const int* __restrict__ cnt, float* __restrict__ dis,
                      float* __restrict__ invd) {
    int i = blockIdx.x * blockDim.x + threadIdx.x;
    if (i < NN) {
        float d = (float)(cnt[i] + 1);
        dis[i]  = rsqrtf(d);
        invd[i] = 1.0f / d;
    }
}

// ---- multi-block scan ----
#define SCB 1024
__global__ void k_scan_blk(const int* __restrict__ cnt, int* __restrict__ off,
                           int* __restrict__ btot, int n) {
    __shared__ int ws[32];
    const unsigned FULL = 0xffffffffu;
    int t = threadIdx.x, w = t >> 5, l = t & 31;
    int i = blockIdx.x * SCB + t;
    int v = (i < n) ? cnt[i] : 0;
    int s = v;
    #pragma unroll
    for (int d = 1; d < 32; d <<= 1) {
        int o = __shfl_up_sync(FULL, s, d);
        if (l >= d) s += o;
    }
    if (l == 31) ws[w] = s;
    __syncthreads();
    if (w == 0) {
        int x2 = ws[l];
        #pragma unroll
        for (int d = 1; d < 32; d <<= 1) {
            int o = __shfl_up_sync(FULL, x2, d);
            if (l >= d) x2 += o;
        }
        ws[l] = x2;
    }
    __syncthreads();
    int incl = s + (w > 0 ? ws[w - 1] : 0);
    if (i < n) off[i] = incl - v;
    if (t == SCB - 1) btot[blockIdx.x] = incl;
}

__global__ void k_scan_tot(int* __restrict__ btot, int nb, int* __restrict__ offN) {
    __shared__ int sh[128];
    int t = threadIdx.x;
    int v = (t < nb) ? btot[t] : 0;
    sh[t] = v;
    __syncthreads();
    #pragma unroll
    for (int d = 1; d < 128; d <<= 1) {
        int o = (t >= d) ? sh[t - d] : 0;
        __syncthreads();
        sh[t] += o;
        __syncthreads();
    }
    if (t < nb) btot[t] = sh[t] - v;
    if (t == 127) *offN = sh[127];
}

__global__ void k_scan_add(int* __restrict__ off, const int* __restrict__ btot,
                           int* __restrict__ cur, int n) {
    int i = blockIdx.x * blockDim.x + threadIdx.x;
    if (i < n) {
        int e = off[i] + btot[i >> 10];
        off[i] = e;
        cur[i] = e;
    }
}

__global__ void k_place(const int* __restrict__ src, const int* __restrict__ dst,
                        const float* __restrict__ dis, int* __restrict__ cur,
                        int* __restrict__ ssrc, float* __restrict__ sw,
                        const int* __restrict__ perm, int* __restrict__ ssrcp) {
    int e = blockIdx.x * blockDim.x + threadIdx.x;
    if (e < NE) {
        int s = src[e], d = dst[e];
        int p = atomicAdd(&cur[d], 1);
        ssrc[p] = s;
        sw[p]   = dis[s] * dis[d];
        if (ssrcp) ssrcp[p] = perm[s];
    }
}

// ================= weight prep: W[K,128] -> Wt[128,K] fp16 =================
__global__ void k_prepw(const float* __restrict__ W, __half* __restrict__ Bt, int K) {
    int i = blockIdx.x * blockDim.x + threadIdx.x;
    if (i < K * 128) {
        int n = i / K, k = i - n * K;
        Bt[(size_t)n * K + k] = __float2half(W[(size_t)k * 128 + n]);
    }
}

// ================= fp16 mma.sync GEMM =================
// C[M,128] = A[M,K] @ B[K,128]; A fp16 row-major, B pre-transposed fp16 [128,K].
// BM=128 BN=128 BK=32, 256 thr, warps 4x2, warp tile 32x64. One MMA pass.
#define STRIDE_B 80
#define ARR_SZ   (128 * STRIDE_B)       // 10240 B (128 rows x 64B data + pad)
#define STAGE_SZ (2 * ARR_SZ)           // 20480 B (A + B)
#define SMEM_SZ  (2 * STAGE_SZ)         // 40960 B double-buffered

__device__ __forceinline__ void wmma_prefetch(
    uint32_t sbase, const __half* A, const __half* B,
    int m0, int M, int K, int k0, int tid)
{
    #pragma unroll
    for (int p = 0; p < 2; p++) {
        int idx = tid + p * 256;
        int row = idx >> 2, cg = idx & 3;
        int gr = m0 + row; if (gr >= M) gr = M - 1;
        size_t aoff = (size_t)gr * K + k0 + cg * 8;
        size_t boff = (size_t)row * K + k0 + cg * 8;
        uint32_t so = row * STRIDE_B + cg * 16;
        cpa16(sbase + 0 * ARR_SZ + so, A + aoff);
        cpa16(sbase + 1 * ARR_SZ + so, B + boff);
    }
}

#define WMMA_MAINLOOP_BODY(st)                                                   \
    {                                                                            \
        _Pragma("unroll")                                                        \
        for (int kk = 0; kk < 2; kk++) {                                         \
            const uint32_t kb = kk * 32;                                         \
            uint32_t ah[2][4], bh[4][4];                                         \
            _Pragma("unroll")                                                    \
            for (int mt = 0; mt < 2; mt++) {                                     \
                uint32_t ao = (st) + aoffs + mt * (16 * STRIDE_B) + kb;          \
                ldsm4(ah[mt], ao + 0 * ARR_SZ);                                  \
            }                                                                    \
            _Pragma("unroll")                                                    \
            for (int np = 0; np < 4; np++) {                                     \
                uint32_t bo = (st) + boffs + np * (16 * STRIDE_B) + kb;          \
                ldsm4(bh[np], bo + 1 * ARR_SZ);                                  \
            }                                                                    \
            _Pragma("unroll")                                                    \
            for (int mt = 0; mt < 2; mt++)                                       \
                _Pragma("unroll")                                                \
                for (int nt = 0; nt < 8; nt++)                                   \
                    mma16816h(c[mt][nt], ah[mt], &bh[nt >> 1][(nt & 1) * 2]);    \
        }                                                                        \
    }

#define WMMA_EPILOGUE()                                                          \
    _Pragma("unroll")                                                            \
    for (int mt = 0; mt < 2; mt++) {                                             \
        _Pragma("unroll")                                                        \
        for (int part = 0; part < 2; part++) {                                   \
            int gr = m0 + wm0 + mt * 16 + (lane >> 2) + part * 8;                \
            if (gr >= M) continue;                                               \
            _Pragma("unroll")                                                    \
            for (int nt = 0; nt < 8; nt++) {                                     \
                int gcol = wn0 + nt * 8 + (lane & 3) * 2;                        \
                float v0 = c[mt][nt][part * 2 + 0];                              \
                float v1 = c[mt][nt][part * 2 + 1];                              \
                if (bias) { v0 += bias[gcol]; v1 += bias[gcol + 1]; }            \
                if (dorelu) { v0 = fmaxf(v0, 0.f); v1 = fmaxf(v1, 0.f); }        \
                if (Cf)                                                          \
                    *(float2*)(Cf + (size_t)gr * FD + gcol) = make_float2(v0, v1); \
                if (Chf) {                                                       \
                    __half2 hh = __floats2half2_rn(v0, v1);                      \
                    *(uint32_t*)(Chf + (size_t)gr * FD + gcol) = *(uint32_t*)&hh; \
                }                                                                \
            }                                                                    \
        }                                                                        \
    }

__global__ void __launch_bounds__(256, 2) k_wmma(
    const __half* __restrict__ A, const __half* __restrict__ B,
    const float* __restrict__ bias, int dorelu,
    float* __restrict__ Cf, __half* __restrict__ Chf, int M, int K)
{
    extern __shared__ char smem[];
    const uint32_t sb = s2u(smem);
    const int tid  = threadIdx.x;
    const int lane = tid & 31, w = tid >> 5;
    const int wm0 = (w >> 1) * 32, wn0 = (w & 1) * 64;
    const int m0  = blockIdx.x * 128;

    float c[2][8][4];
    #pragma unroll
    for (int i = 0; i < 2; i++)
        #pragma unroll
        for (int j = 0; j < 8; j++)
            #pragma unroll
            for (int q = 0; q < 4; q++) c[i][j][q] = 0.f;

    const uint32_t aoffs = (uint32_t)((wm0 + (lane & 15)) * STRIDE_B + (lane >> 4) * 16);
    const uint32_t boffs = (uint32_t)((wn0 + ((lane >> 4) & 1) * 8 + (lane & 7)) * STRIDE_B
                                      + ((lane >> 3) & 1) * 16);

    const int nch = K >> 5;
    wmma_prefetch(sb, A, B, m0, M, K, 0, tid);
    CP_COMMIT();

    for (int ch = 0; ch < nch; ch++) {
        if (ch + 1 < nch) {
            wmma_prefetch(sb + ((ch + 1) & 1) * STAGE_SZ, A, B,
                          m0, M, K, (ch + 1) << 5, tid);
            CP_COMMIT();
            CP_WAIT1();
        } else {
            CP_WAIT0();
        }
        __syncthreads();
        const uint32_t st = sb + (ch & 1) * STAGE_SZ;
        WMMA_MAINLOOP_BODY(st)
        __syncthreads();
    }
    WMMA_EPILOGUE()
}

// ---- variant: A is f32, converted to fp16 on the fly (for x @ W1) ----
__global__ void __launch_bounds__(256, 2) k_wmmaX(
    const float* __restrict__ Af, const __half* __restrict__ B,
    const float* __restrict__ bias, int dorelu,
    float* __restrict__ Cf, __half* __restrict__ Chf, int M, int K)
{
    extern __shared__ char smem[];
    const uint32_t sb = s2u(smem);
    const int tid  = threadIdx.x;
    const int lane = tid & 31, w = tid >> 5;
    const int wm0 = (w >> 1) * 32, wn0 = (w & 1) * 64;
    const int m0  = blockIdx.x * 128;

    float c[2][8][4];
    #pragma unroll
    for (int i = 0; i < 2; i++)
        #pragma unroll
        for (int j = 0; j < 8; j++)
            #pragma unroll
            for (int q = 0; q < 4; q++) c[i][j][q] = 0.f;

    const uint32_t aoffs = (uint32_t)((wm0 + (lane & 15)) * STRIDE_B + (lane >> 4) * 16);
    const uint32_t boffs = (uint32_t)((wn0 + ((lane >> 4) & 1) * 8 + (lane & 7)) * STRIDE_B
                                      + ((lane >> 3) & 1) * 16);

    const int nch = K >> 5;

    #define PREFETCH_X(sbase, k0)                                                 \
    {                                                                             \
        _Pragma("unroll")                                                         \
        for (int p = 0; p < 2; p++) {                                             \
            int idx = tid + p * 256;                                              \
            int row = idx >> 2, cg = idx & 3;                                     \
            int gr = m0 + row; if (gr >= M) gr = M - 1;                           \
            size_t aoff = (size_t)gr * K + (k0) + cg * 8;                         \
            size_t boff = (size_t)row * K + (k0) + cg * 8;                        \
            uint32_t so = row * STRIDE_B + cg * 16;                               \
            cpa16((sbase) + 1 * ARR_SZ + so, B + boff);                           \
            float4 v0 = *(const float4*)(Af + aoff);                              \
            float4 v1 = *(const float4*)(Af + aoff + 4);                          \
            __half2 h0 = __floats2half2_rn(v0.x, v0.y);                           \
            __half2 h1 = __floats2half2_rn(v0.z, v0.w);                           \
            __half2 h2 = __floats2half2_rn(v1.x, v1.y);                           \
            __half2 h3 = __floats2half2_rn(v1.z, v1.w);                           \
            asm volatile("st.shared.v4.b32 [%0], {%1,%2,%3,%4};"                  \
                :: "r"((sbase) + 0 * ARR_SZ + so),                                \
                   "r"(*(uint32_t*)&h0), "r"(*(uint32_t*)&h1),                    \
                   "r"(*(uint32_t*)&h2), "r"(*(uint32_t*)&h3) : "memory");        \
        }                                                                         \
    }

    PREFETCH_X(sb, 0)
    CP_COMMIT();

    for (int ch = 0; ch < nch; ch++) {
        if (ch + 1 < nch) {
            PREFETCH_X(sb + ((ch + 1) & 1) * STAGE_SZ, (ch + 1) << 5)
            CP_COMMIT();
            CP_WAIT1();
        } else {
            CP_WAIT0();
        }
        __syncthreads();
        const uint32_t st = sb + (ch & 1) * STAGE_SZ;
        WMMA_MAINLOOP_BODY(st)
        __syncthreads();
    }
    WMMA_EPILOGUE()
    #undef PREFETCH_X
}

// ======== gather aggregation (fp16 rows in, fp32 accum, fp16/f32 out) ========
__global__ void k_agg(const __half* __restrict__ h, const int* __restrict__ off,
                      const int* __restrict__ ssrc, const float* __restrict__ sw,
                      const float* __restrict__ invd, const float* __restrict__ bias,
                      const int* __restrict__ selfmap,
                      float* __restrict__ outf, __half* __restrict__ outh, int dorelu)
{
    int node = (blockIdx.x * blockDim.x + threadIdx.x) >> 5;
    int lane = threadIdx.x & 31;
    if (node >= NN) return;
    int s = off[node], e = off[node + 1];
    float4 acc = make_float4(0.f, 0.f, 0.f, 0.f);
    for (int i = s; i < e; i++) {
        int   src = ssrc[i];
        float w   = sw[i];
        uint2 raw = *(const uint2*)(h + (size_t)src * FD + lane * 4);
        float2 f0 = __half22float2(*(__half2*)&raw.x);
        float2 f1 = __half22float2(*(__half2*)&raw.y);
        acc.x = fmaf(w, f0.x, acc.x);
        acc.y = fmaf(w, f0.y, acc.y);
        acc.z = fmaf(w, f1.x, acc.z);
        acc.w = fmaf(w, f1.y, acc.w);
    }
    int self = selfmap ? selfmap[node] : node;
    float id = invd[node];
    uint2 rs = *(const uint2*)(h + (size_t)self * FD + lane * 4);
    float2 s0 = __half22float2(*(__half2*)&rs.x);
    float2 s1 = __half22float2(*(__half2*)&rs.y);
    float4 b = *(const float4*)(bias + lane * 4);
    acc.x = fmaf(id, s0.x, acc.x) + b.x;
    acc.y = fmaf(id, s0.y, acc.y) + b.y;
    acc.z = fmaf(id, s1.x, acc.z) + b.z;
    acc.w = fmaf(id, s1.y, acc.w) + b.w;
    if (dorelu) {
        acc.x = fmaxf(acc.x, 0.f); acc.y = fmaxf(acc.y, 0.f);
        acc.z = fmaxf(acc.z, 0.f); acc.w = fmaxf(acc.w, 0.f);
    }
    if (outf)
        *(float4*)(outf + (size_t)node * FD + lane * 4) = acc;
    if (outh) {
        __half2 o0 = __floats2half2_rn(acc.x, acc.y);
        __half2 o1 = __floats2half2_rn(acc.z, acc.w);
        *(uint2*)(outh + (size_t)node * FD + lane * 4) =
            make_uint2(*(uint32_t*)&o0, *(uint32_t*)&o1);
    }
}

// ===== fused hop-agg + bilinear score (fp16 G rows) =====
__global__ void k_aggscore(const __half* __restrict__ G, const float* __restrict__ T,
                           const int* __restrict__ off, const int* __restrict__ ssrc,
                           const float* __restrict__ sw, const float* __restrict__ invd,
                           const float* __restrict__ b3, float* __restrict__ out,
                           int col)
{
    const unsigned FULL = 0xffffffffu;
    int node = (blockIdx.x * blockDim.x + threadIdx.x) >> 5;
    int lane = threadIdx.x & 31;
    if (node >= NN) return;
    float4 tv = *(const float4*)(T + (size_t)node * FD + lane * 4);
    int s = off[node], e = off[node + 1];
    float acc = 0.f;
    for (int i = s; i < e; i++) {
        int   src = ssrc[i];
        float w   = sw[i];
        uint2 raw = *(const uint2*)(G + (size_t)src * FD + lane * 4);
        float2 f0 = __half22float2(*(__half2*)&raw.x);
        float2 f1 = __half22float2(*(__half2*)&raw.y);
        acc = fmaf(w, tv.x * f0.x + tv.y * f0.y + tv.z * f1.x + tv.w * f1.y, acc);
    }
    uint2 rs = *(const uint2*)(G + (size_t)node * FD + lane * 4);
    float2 s0 = __half22float2(*(__half2*)&rs.x);
    float2 s1 = __half22float2(*(__half2*)&rs.y);
    float4 bb = *(const float4*)(b3 + lane * 4);
    acc = fmaf(invd[node], tv.x * s0.x + tv.y * s0.y + tv.z * s1.x + tv.w * s1.y, acc);
    acc += tv.x * bb.x + tv.y * bb.y + tv.z * bb.z + tv.w * bb.w;
    #pragma unroll
    for (int d = 16; d > 0; d >>= 1) acc += __shfl_xor_sync(FULL, acc, d);
    if (lane == 0)
        out[(size_t)node * OUTC + col] = 1.0f / (1.0f + expf(-acc));
}

// ================= classifier =================
__global__ void k_gemm10(const float* __restrict__ A, const float* __restrict__ W,
                         float* __restrict__ C)
{
    __shared__ float w[FD * NC];
    for (int i = threadIdx.x; i < FD * NC; i += blockDim.x) w[i] = W[i];
    __syncthreads();
    int r = blockIdx.x * blockDim.x + threadIdx.x;
    if (r >= NN) return;
    float acc[NC];
    #pragma unroll
    for (int j = 0; j < NC; j++) acc[j] = 0.f;
    const float4* ap = (const float4*)(A + (size_t)r * FD);
    #pragma unroll 8
    for (int k4 = 0; k4 < 32; k4++) {
        float4 v = ap[k4];
        int k = k4 * 4;
        #pragma unroll
        for (int j = 0; j < NC; j++) {
            acc[j] = fmaf(v.x, w[(k + 0) * NC + j], acc[j]);
            acc[j] = fmaf(v.y, w[(k + 1) * NC + j], acc[j]);
            acc[j] = fmaf(v.z, w[(k + 2) * NC + j], acc[j]);
            acc[j] = fmaf(v.w, w[(k + 3) * NC + j], acc[j]);
        }
    }
    #pragma unroll
    for (int j = 0; j < NC; j++) C[(size_t)r * NC + j] = acc[j];
}

__global__ void k_agg10(const float* __restrict__ h, const int* __restrict__ off,
                        const int* __restrict__ ssrc, const float* __restrict__ sw,
                        const float* __restrict__ invd, const float* __restrict__ bc,
                        float* __restrict__ out)
{
    int node = (blockIdx.x * blockDim.x + threadIdx.x) >> 5;
    int lane = threadIdx.x & 31;
    if (node >= NN || lane >= NC) return;
    int s = off[node], e = off[node + 1];
    float acc = 0.f;
    for (int i = s; i < e; i++) {
        int src = ssrc[i];
        acc = fmaf(sw[i], h[(size_t)src * NC + lane], acc);
    }
    acc = fmaf(invd[node], h[(size_t)node * NC + lane], acc) + bc[lane];
    out[(size_t)node * OUTC + lane] = acc;
}

// ================= host =================
extern "C" void kernel_launch(void* const* d_in, const int* in_sizes, int n_in,
                              void* d_out, int out_size)
{
    const float* x    = (const float*)d_in[0];
    const int*   ei   = (const int*)  d_in[1];
    const int*   eh   = (const int*)  d_in[2];
    const int*   perm = (const int*)  d_in[4];
    const float* W1   = (const float*)d_in[5];
    const float* b1   = (const float*)d_in[6];
    const float* W2   = (const float*)d_in[7];
    const float* b2   = (const float*)d_in[8];
    const float* W3   = (const float*)d_in[9];
    const float* b3   = (const float*)d_in[10];
    const float* M1   = (const float*)d_in[11];
    const float* mb1  = (const float*)d_in[12];
    const float* M2   = (const float*)d_in[13];
    const float* mb2  = (const float*)d_in[14];
    const float* Wc   = (const float*)d_in[15];
    const float* bc   = (const float*)d_in[16];
    const float* Wd   = (const float*)d_in[17];
    float* out = (float*)d_out;

    float *EAf, *T, *C10, *dis, *invd, *sw;
    __half *Hh, *P1, *Gh, *P2, *P3, *P4, *Wf;
    int *cnt, *off, *cur, *btot, *ssrc, *ssrcp;
    cudaGetSymbolAddress((void**)&Hh,   g_Hh);
    cudaGetSymbolAddress((void**)&P1,   g_P1);
    cudaGetSymbolAddress((void**)&Gh,   g_Gh);
    cudaGetSymbolAddress((void**)&P2,   g_P2);
    cudaGetSymbolAddress((void**)&P3,   g_P3);
    cudaGetSymbolAddress((void**)&P4,   g_P4);
    cudaGetSymbolAddress((void**)&EAf,  g_EAf);
    cudaGetSymbolAddress((void**)&T,    g_T);
    cudaGetSymbolAddress((void**)&C10,  g_C10);
    cudaGetSymbolAddress((void**)&Wf,   g_Wf);
    cudaGetSymbolAddress((void**)&cnt,  g_cnt);
    cudaGetSymbolAddress((void**)&dis,  g_dis);
    cudaGetSymbolAddress((void**)&invd, g_invd);
    cudaGetSymbolAddress((void**)&off,  g_off);
    cudaGetSymbolAddress((void**)&cur,  g_cur);
    cudaGetSymbolAddress((void**)&btot, g_btot);
    cudaGetSymbolAddress((void**)&ssrc, g_ssrc);
    cudaGetSymbolAddress((void**)&ssrcp,g_ssrcp);
    cudaGetSymbolAddress((void**)&sw,   g_sw);

    cudaFuncSetAttribute(k_wmma,  cudaFuncAttributeMaxDynamicSharedMemorySize, SMEM_SZ);
    cudaFuncSetAttribute(k_wmmaX, cudaFuncAttributeMaxDynamicSharedMemorySize, SMEM_SZ);

    const int TE  = 256;
    const int GE  = (NE + TE - 1) / TE;
    const int GN  = (NN + TE - 1) / TE;
    const int GW  = (NN * 32 + TE - 1) / TE;
    const int GM  = (NN + 127) / 128;
    const int GM2 = (2 * NN + 127) / 128;
    const int NB  = (NN + SCB - 1) / SCB;
    const size_t HB = (size_t)NN * FD;

    // ---- prologue (node 5 = k_wmmaX for ncu) ----
    cudaMemsetAsync(cnt, 0, sizeof(int) * 2 * NN);
    k_count<<<GE, TE>>>(ei + NE, cnt);
    k_prepw<<<(512 * 128 + 255) / 256, 256>>>(W1, Wf + WOFF_W1, 512);
    k_deg<<<GN, TE>>>(cnt, dis, invd);
    k_wmmaX<<<GM, 256, SMEM_SZ>>>(x, Wf + WOFF_W1, nullptr, 0,
                                  nullptr, Hh, NN, 512);
    k_count<<<GE, TE>>>(eh + NE, cnt + NN);
    k_deg<<<GN, TE>>>(cnt + NN, dis + NN, invd + NN);

    // ---- multi-block scans ----
    k_scan_blk<<<NB, SCB>>>(cnt, off, btot, NN);
    k_scan_tot<<<1, 128>>>(btot, NB, off + NN);
    k_scan_add<<<GN, TE>>>(off, btot, cur, NN);
    k_scan_blk<<<NB, SCB>>>(cnt + NN, off + (NN + 1), btot + 128, NN);
    k_scan_tot<<<1, 128>>>(btot + 128, NB, off + (NN + 1) + NN);
    k_scan_add<<<GN, TE>>>(off + (NN + 1), btot + 128, cur + NN, NN);

    k_place<<<GE, TE>>>(ei, ei + NE, dis,      cur,      ssrc,      sw,
                        perm, ssrcp);
    k_place<<<GE, TE>>>(eh, eh + NE, dis + NN, cur + NN, ssrc + NE, sw + NE,
                        nullptr, nullptr);

    // ---- remaining weight prep ----
    k_prepw<<<(128 * 128 + 255) / 256, 256>>>(W2, Wf + WOFF_W2, 128);
    k_prepw<<<(128 * 128 + 255) / 256, 256>>>(W3, Wf + WOFF_W3, 128);
    k_prepw<<<(128 * 128 + 255) / 256, 256>>>(M1, Wf + WOFF_M1, 128);
    k_prepw<<<(128 * 128 + 255) / 256, 256>>>(M2, Wf + WOFF_M2, 128);
    k_prepw<<<(128 * 128 + 255) / 256, 256>>>(Wd, Wf + WOFF_WD, 128);

    // ---- layer1 aggs back-to-back (Hh warm in L2, 25.6 MB) ----
    k_agg<<<GW, TE>>>(Hh, off, ssrc,  sw, invd, b1, nullptr, nullptr, P1, 1);
    k_agg<<<GW, TE>>>(Hh, off, ssrcp, sw, invd, b1, perm, nullptr, P1 + HB, 1);

    // ---- batched W2 GEMM over both halves -> Gh ----
    k_wmma<<<GM2, 256, SMEM_SZ>>>(P1, Wf + WOFF_W2, nullptr, 0,
                                  nullptr, Gh, 2 * NN, 128);

    // ---- good half ----
    k_agg<<<GW, TE>>>(Gh, off, ssrc, sw, invd, b2, nullptr, EAf, P2, 1);
    k_wmma<<<GM, 256, SMEM_SZ>>>(P2, Wf + WOFF_M1, mb1, 1, nullptr, P3, NN, 128);
    k_gemm10<<<GN, TE>>>(EAf, Wc, C10);
    k_agg10<<<GW, TE>>>(C10, off, ssrc, sw, invd, bc, out);
    k_wmma<<<GM, 256, SMEM_SZ>>>(P3, Wf + WOFF_M2, mb2, 0, nullptr, P4, NN, 128);
    k_wmma<<<GM, 256, SMEM_SZ>>>(P4, Wf + WOFF_WD, nullptr, 0, T, nullptr, NN, 128);
    k_wmma<<<GM, 256, SMEM_SZ>>>(P2, Wf + WOFF_W3, nullptr, 0, nullptr, Gh, NN, 128);
    k_aggscore<<<GW, TE>>>(Gh, T, off + (NN + 1), ssrc + NE, sw + NE, invd + NN,
                           b3, out, 10);

    // ---- bad half ----
    k_agg<<<GW, TE>>>(Gh + HB, off, ssrc, sw, invd, b2, nullptr,
                      nullptr, P2 + HB, 1);
    k_wmma<<<GM, 256, SMEM_SZ>>>(P2 + HB, Wf + WOFF_W3, nullptr, 0,
                                 nullptr, Gh, NN, 128);
    k_aggscore<<<GW, TE>>>(Gh, T, off + (NN + 1), ssrc + NE, sw + NE, invd + NN,
                           b3, out, 11);
}

// round 14
// speedup vs baseline: 1.3829x; 1.0545x over previous
#include <cuda_runtime.h>
#include <cuda_fp16.h>
#include <math.h>
#include <stdint.h>

#define NN 100000
#define NE 1600000
#define NF 512
#define FD 128
#define NC 10
#define OUTC 12

// ================= PTX helpers (sm_80-compatible only) =================
__device__ __forceinline__ uint32_t s2u(const void* p) {
    uint32_t a;
    asm("{ .reg .u64 t; cvta.to.shared.u64 t, %1; cvt.u32.u64 %0, t; }"
        : "=r"(a) : "l"(p));
    return a;
}
__device__ __forceinline__ void cpa16(uint32_t dst, const void* src) {
    asm volatile("cp.async.cg.shared.global [%0], [%1], 16;" :: "r"(dst), "l"(src));
}
#define CP_COMMIT() asm volatile("cp.async.commit_group;" ::: "memory")
#define CP_WAIT1()  asm volatile("cp.async.wait_group 1;" ::: "memory")
#define CP_WAIT0()  asm volatile("cp.async.wait_group 0;" ::: "memory")

__device__ __forceinline__ void ldsm4(uint32_t* r, uint32_t addr) {
    asm volatile("ldmatrix.sync.aligned.m8n8.x4.shared.b16 {%0,%1,%2,%3}, [%4];"
                 : "=r"(r[0]), "=r"(r[1]), "=r"(r[2]), "=r"(r[3]) : "r"(addr));
}
__device__ __forceinline__ void mma16816h(float* c, const uint32_t* a, const uint32_t* b) {
    asm volatile("mma.sync.aligned.m16n8k16.row.col.f32.f16.f16.f32 "
                 "{%0,%1,%2,%3}, {%4,%5,%6,%7}, {%8,%9}, {%0,%1,%2,%3};"
                 : "+f"(c[0]), "+f"(c[1]), "+f"(c[2]), "+f"(c[3])
                 : "r"(a[0]), "r"(a[1]), "r"(a[2]), "r"(a[3]), "r"(b[0]), "r"(b[1]));
}

// ================= scratch (device globals) =================
__device__ __half g_Hh [(size_t)NN * FD];
__device__ __half g_P1 [(size_t)2 * NN * FD];
__device__ __half g_Gh [(size_t)2 * NN * FD];
__device__ __half g_P2 [(size_t)2 * NN * FD];
__device__ __half g_P3 [(size_t)NN * FD];
__device__ __half g_P4 [(size_t)NN * FD];
__device__ float g_T  [(size_t)NN * FD];
__device__ float g_C10[(size_t)NN * NC];
#define WOFF_W1 0
#define WOFF_W2 (128 * 512)
#define WOFF_W3 (WOFF_W2 + 128 * 128)
#define WOFF_M1 (WOFF_W3 + 128 * 128)
#define WOFF_M2 (WOFF_M1 + 128 * 128)
#define WOFF_WD (WOFF_M2 + 128 * 128)
#define WTOT    (WOFF_WD + 128 * 128)
__device__ __half g_Wf[WTOT];
__device__ int   g_cnt [2 * NN];
__device__ float g_dis [2 * NN];
__device__ float g_invd[2 * NN];
__device__ int   g_off [2 * (NN + 1)];
__device__ int   g_cur [2 * NN];
__device__ int   g_btot[2 * 128];
__device__ int   g_ssrc[2 * NE];
__device__ int   g_ssrcp[NE];
__device__ float g_sw  [2 * NE];

// ================= CSR build (merged kernels) =================
__global__ void k_count2(const int* __restrict__ d0, const int* __restrict__ d1,
                         int* __restrict__ cnt) {
    int i = blockIdx.x * blockDim.x + threadIdx.x;
    if (i < NE) atomicAdd(&cnt[d0[i]], 1);
    else {
        int j = i - NE;
        if (j < NE) atomicAdd(&cnt[NN + d1[j]], 1);
    }
}

__global__ void k_deg2(const int* __restrict__ cnt, float* __restrict__ dis,
                       float* __restrict__ invd) {
    int i = blockIdx.x * blockDim.x + threadIdx.x;
    if (i < 2 * NN) {
        float d = (float)(cnt[i] + 1);
        dis[i]  = rsqrtf(d);
        invd[i] = 1.0f / d;
    }
}

#define SCB 1024
#define NB  ((NN + SCB - 1) / SCB)   // 98
__global__ void k_scan_blk2(const int* __restrict__ cnt, int* __restrict__ off,
                            int* __restrict__ btot) {
    __shared__ int ws[32];
    const unsigned FULL = 0xffffffffu;
    int g = blockIdx.x / NB, b = blockIdx.x % NB;
    const int* c = cnt + g * NN;
    int* o  = off + g * (NN + 1);
    int* bt = btot + g * 128;
    int t = threadIdx.x, w = t >> 5, l = t & 31;
    int i = b * SCB + t;
    int v = (i < NN) ? c[i] : 0;
    int s = v;
    #pragma unroll
    for (int d = 1; d < 32; d <<= 1) {
        int oo = __shfl_up_sync(FULL, s, d);
        if (l >= d) s += oo;
    }
    if (l == 31) ws[w] = s;
    __syncthreads();
    if (w == 0) {
        int x2 = ws[l];
        #pragma unroll
        for (int d = 1; d < 32; d <<= 1) {
            int oo = __shfl_up_sync(FULL, x2, d);
            if (l >= d) x2 += oo;
        }
        ws[l] = x2;
    }
    __syncthreads();
    int incl = s + (w > 0 ? ws[w - 1] : 0);
    if (i < NN) o[i] = incl - v;
    if (t == SCB - 1) bt[b] = incl;
}

__global__ void k_scan_tot2(int* __restrict__ btot, int* __restrict__ off) {
    __shared__ int sh[128];
    int g = blockIdx.x;
    int* bt = btot + g * 128;
    int t = threadIdx.x;
    int v = (t < NB) ? bt[t] : 0;
    sh[t] = v;
    __syncthreads();
    #pragma unroll
    for (int d = 1; d < 128; d <<= 1) {
        int o = (t >= d) ? sh[t - d] : 0;
        __syncthreads();
        sh[t] += o;
        __syncthreads();
    }
    if (t < NB) bt[t] = sh[t] - v;
    if (t == 127) off[g * (NN + 1) + NN] = sh[127];
}

__global__ void k_scan_add2(int* __restrict__ off, const int* __restrict__ btot,
                            int* __restrict__ cur, int gpb) {
    int g = blockIdx.x / gpb;
    int i = (blockIdx.x % gpb) * blockDim.x + threadIdx.x;
    if (i < NN) {
        int e = off[g * (NN + 1) + i] + btot[g * 128 + (i >> 10)];
        off[g * (NN + 1) + i] = e;
        cur[g * NN + i] = e;
    }
}

__global__ void k_place2(const int* __restrict__ ei, const int* __restrict__ eh,
                         const float* __restrict__ dis, int* __restrict__ cur,
                         int* __restrict__ ssrc, float* __restrict__ sw,
                         const int* __restrict__ perm, int* __restrict__ ssrcp) {
    int gi = blockIdx.x * blockDim.x + threadIdx.x;
    if (gi < NE) {
        int s = ei[gi], d = ei[NE + gi];
        int p = atomicAdd(&cur[d], 1);
        ssrc[p]  = s;
        sw[p]    = dis[s] * dis[d];
        ssrcp[p] = perm[s];
    } else {
        int e = gi - NE;
        if (e < NE) {
            int s = eh[e], d = eh[NE + e];
            int p = atomicAdd(&cur[NN + d], 1);
            ssrc[NE + p] = s;
            sw[NE + p]   = dis[NN + s] * dis[NN + d];
        }
    }
}

// ================= weight prep =================
__global__ void k_prepw(const float* __restrict__ W, __half* __restrict__ Bt, int K) {
    int i = blockIdx.x * blockDim.x + threadIdx.x;
    if (i < K * 128) {
        int n = i / K, k = i - n * K;
        Bt[(size_t)n * K + k] = __float2half(W[(size_t)k * 128 + n]);
    }
}

// all 5 128x128 weights in one launch
__global__ void k_prepw5(const float* __restrict__ W2, const float* __restrict__ W3,
                         const float* __restrict__ M1, const float* __restrict__ M2,
                         const float* __restrict__ Wd, __half* __restrict__ Wf) {
    int i = blockIdx.x * blockDim.x + threadIdx.x;
    if (i >= 5 * 128 * 128) return;
    int r = i >> 14, j = i & 16383;
    const float* W = (r == 0) ? W2 : (r == 1) ? W3 : (r == 2) ? M1 : (r == 3) ? M2 : Wd;
    int woff = (r == 0) ? WOFF_W2 : (r == 1) ? WOFF_W3 : (r == 2) ? WOFF_M1
             : (r == 3) ? WOFF_M2 : WOFF_WD;
    int n = j >> 7, k = j & 127;
    Wf[woff + (size_t)n * 128 + k] = __float2half(W[(size_t)k * 128 + n]);
}

// ================= fp16 mma.sync GEMM =================
#define STRIDE_B 80
#define ARR_SZ   (128 * STRIDE_B)       // 10240
#define STAGE_SZ (2 * ARR_SZ)           // 20480 (A + B)
#define SMEM_SZ  (2 * STAGE_SZ)         // 40960

__device__ __forceinline__ void wmma_prefetch(
    uint32_t sbase, const __half* A, const __half* B,
    int m0, int M, int K, int k0, int tid)
{
    #pragma unroll
    for (int p = 0; p < 2; p++) {
        int idx = tid + p * 256;
        int row = idx >> 2, cg = idx & 3;
        int gr = m0 + row; if (gr >= M) gr = M - 1;
        size_t aoff = (size_t)gr * K + k0 + cg * 8;
        size_t boff = (size_t)row * K + k0 + cg * 8;
        uint32_t so = row * STRIDE_B + cg * 16;
        cpa16(sbase + 0 * ARR_SZ + so, A + aoff);
        cpa16(sbase + 1 * ARR_SZ + so, B + boff);
    }
}

#define WMMA_MAINLOOP_BODY(st)                                                   \
    {                                                                            \
        _Pragma("unroll")                                                        \
        for (int kk = 0; kk < 2; kk++) {                                         \
            const uint32_t kb = kk * 32;                                         \
            uint32_t ah[2][4], bh[4][4];                                         \
            _Pragma("unroll")                                                    \
            for (int mt = 0; mt < 2; mt++) {                                     \
                uint32_t ao = (st) + aoffs + mt * (16 * STRIDE_B) + kb;          \
                ldsm4(ah[mt], ao + 0 * ARR_SZ);                                  \
            }                                                                    \
            _Pragma("unroll")                                                    \
            for (int np = 0; np < 4; np++) {                                     \
                uint32_t bo = (st) + boffs + np * (16 * STRIDE_B) + kb;          \
                ldsm4(bh[np], bo + 1 * ARR_SZ);                                  \
            }                                                                    \
            _Pragma("unroll")                                                    \
            for (int mt = 0; mt < 2; mt++)                                       \
                _Pragma("unroll")                                                \
                for (int nt = 0; nt < 8; nt++)                                   \
                    mma16816h(c[mt][nt], ah[mt], &bh[nt >> 1][(nt & 1) * 2]);    \
        }                                                                        \
    }

#define WMMA_EPILOGUE()                                                          \
    _Pragma("unroll")                                                            \
    for (int mt = 0; mt < 2; mt++) {                                             \
        _Pragma("unroll")                                                        \
        for (int part = 0; part < 2; part++) {                                   \
            int gr = m0 + wm0 + mt * 16 + (lane >> 2) + part * 8;                \
            if (gr >= M) continue;                                               \
            _Pragma("unroll")                                                    \
            for (int nt = 0; nt < 8; nt++) {                                     \
                int gcol = wn0 + nt * 8 + (lane & 3) * 2;                        \
                float v0 = c[mt][nt][part * 2 + 0];                              \
                float v1 = c[mt][nt][part * 2 + 1];                              \
                if (bias) { v0 += bias[gcol]; v1 += bias[gcol + 1]; }            \
                if (dorelu) { v0 = fmaxf(v0, 0.f); v1 = fmaxf(v1, 0.f); }        \
                if (Cf)                                                          \
                    *(float2*)(Cf + (size_t)gr * FD + gcol) = make_float2(v0, v1); \
                if (Chf) {                                                       \
                    __half2 hh = __floats2half2_rn(v0, v1);                      \
                    *(uint32_t*)(Chf + (size_t)gr * FD + gcol) = *(uint32_t*)&hh; \
                }                                                                \
            }                                                                    \
        }                                                                        \
    }

__global__ void __launch_bounds__(256, 2) k_wmma(
    const __half* __restrict__ A, const __half* __restrict__ B,
    const float* __restrict__ bias, int dorelu,
    float* __restrict__ Cf, __half* __restrict__ Chf, int M, int K)
{
    extern __shared__ char smem[];
    const uint32_t sb = s2u(smem);
    const int tid  = threadIdx.x;
    const int lane = tid & 31, w = tid >> 5;
    const int wm0 = (w >> 1) * 32, wn0 = (w & 1) * 64;
    const int m0  = blockIdx.x * 128;

    float c[2][8][4];
    #pragma unroll
    for (int i = 0; i < 2; i++)
        #pragma unroll
        for (int j = 0; j < 8; j++)
            #pragma unroll
            for (int q = 0; q < 4; q++) c[i][j][q] = 0.f;

    const uint32_t aoffs = (uint32_t)((wm0 + (lane & 15)) * STRIDE_B + (lane >> 4) * 16);
    const uint32_t boffs = (uint32_t)((wn0 + ((lane >> 4) & 1) * 8 + (lane & 7)) * STRIDE_B
                                      + ((lane >> 3) & 1) * 16);

    const int nch = K >> 5;
    wmma_prefetch(sb, A, B, m0, M, K, 0, tid);
    CP_COMMIT();

    for (int ch = 0; ch < nch; ch++) {
        if (ch + 1 < nch) {
            wmma_prefetch(sb + ((ch + 1) & 1) * STAGE_SZ, A, B,
                          m0, M, K, (ch + 1) << 5, tid);
            CP_COMMIT();
            CP_WAIT1();
        } else {
            CP_WAIT0();
        }
        __syncthreads();
        const uint32_t st = sb + (ch & 1) * STAGE_SZ;
        WMMA_MAINLOOP_BODY(st)
        __syncthreads();
    }
    WMMA_EPILOGUE()
}

// ---- variant: A is f32, cp.async-staged + in-smem convert (for x @ W1) ----
// Stage layout: [0, XARR) f32 A staging, [XARR, XARR+ARR_SZ) A fp16,
//               [XARR+ARR_SZ, XARR+2*ARR_SZ) B fp16.
#define XST   144                       // f32 staging row stride (128B data + pad)
#define XARR  (128 * XST)               // 18432
#define XSTG  (XARR + 2 * ARR_SZ)       // 38912
#define XSMEM (2 * XSTG)                // 77824

__global__ void __launch_bounds__(256, 2) k_wmmaX(
    const float* __restrict__ Af, const __half* __restrict__ B,
    const float* __restrict__ bias, int dorelu,
    float* __restrict__ Cf, __half* __restrict__ Chf, int M, int K)
{
    extern __shared__ char smem[];
    const uint32_t sb = s2u(smem);
    const int tid  = threadIdx.x;
    const int lane = tid & 31, w = tid >> 5;
    const int wm0 = (w >> 1) * 32, wn0 = (w & 1) * 64;
    const int m0  = blockIdx.x * 128;

    float c[2][8][4];
    #pragma unroll
    for (int i = 0; i < 2; i++)
        #pragma unroll
        for (int j = 0; j < 8; j++)
            #pragma unroll
            for (int q = 0; q < 4; q++) c[i][j][q] = 0.f;

    const uint32_t aoffs = (uint32_t)((wm0 + (lane & 15)) * STRIDE_B + (lane >> 4) * 16);
    const uint32_t boffs = (uint32_t)((wn0 + ((lane >> 4) & 1) * 8 + (lane & 7)) * STRIDE_B
                                      + ((lane >> 3) & 1) * 16);

    const int nch = K >> 5;

    // async prefetch: B fp16 (2/thread) + A f32 staging (4/thread, 16B each)
    #define PFX(sbase, k0)                                                        \
    {                                                                             \
        _Pragma("unroll")                                                         \
        for (int p = 0; p < 2; p++) {                                             \
            int idx = tid + p * 256;                                              \
            int row = idx >> 2, cg = idx & 3;                                     \
            size_t boff = (size_t)row * K + (k0) + cg * 8;                        \
            cpa16((sbase) + XARR + ARR_SZ + row * STRIDE_B + cg * 16, B + boff);  \
        }                                                                         \
        _Pragma("unroll")                                                         \
        for (int q = 0; q < 4; q++) {                                             \
            int idx = tid + q * 256;                                              \
            int row = idx >> 3, cg = idx & 7;                                     \
            int gr = m0 + row; if (gr >= M) gr = M - 1;                           \
            size_t aoff = (size_t)gr * K + (k0) + cg * 4;                         \
            cpa16((sbase) + row * XST + cg * 16, Af + aoff);                      \
        }                                                                         \
    }

    // in-smem convert: staging f32 -> A fp16
    #define CVTX(sbase)                                                           \
    {                                                                             \
        _Pragma("unroll")                                                         \
        for (int q = 0; q < 4; q++) {                                             \
            int idx = tid + q * 256;                                              \
            int row = idx >> 3, cg = idx & 7;                                     \
            uint32_t sa = (sbase) + row * XST + cg * 16;                          \
            float vx, vy, vz, vw;                                                 \
            asm volatile("ld.shared.v4.f32 {%0,%1,%2,%3}, [%4];"                  \
                : "=f"(vx), "=f"(vy), "=f"(vz), "=f"(vw) : "r"(sa));              \
            __half2 h0 = __floats2half2_rn(vx, vy);                               \
            __half2 h1 = __floats2half2_rn(vz, vw);                               \
            asm volatile("st.shared.v2.b32 [%0], {%1,%2};"                        \
                :: "r"((sbase) + XARR + row * STRIDE_B + cg * 8),                 \
                   "r"(*(uint32_t*)&h0), "r"(*(uint32_t*)&h1) : "memory");        \
        }                                                                         \
    }

    PFX(sb, 0)
    CP_COMMIT();

    for (int ch = 0; ch < nch; ch++) {
        if (ch + 1 < nch) {
            PFX(sb + ((ch + 1) & 1) * XSTG, (ch + 1) << 5)
            CP_COMMIT();
            CP_WAIT1();
        } else {
            CP_WAIT0();
        }
        __syncthreads();
        const uint32_t stg = sb + (ch & 1) * XSTG;
        CVTX(stg)
        __syncthreads();
        WMMA_MAINLOOP_BODY(stg + XARR)   // A at +0*ARR_SZ, B at +1*ARR_SZ
        __syncthreads();
    }
    WMMA_EPILOGUE()
    #undef PFX
    #undef CVTX
}

// ======== gather aggregation (fp16 rows in, fp32 accum, fp16 out) ========
__global__ void k_agg(const __half* __restrict__ h, const int* __restrict__ off,
                      const int* __restrict__ ssrc, const float* __restrict__ sw,
                      const float* __restrict__ invd, const float* __restrict__ bias,
                      const int* __restrict__ selfmap,
                      __half* __restrict__ outh, int dorelu)
{
    int node = (blockIdx.x * blockDim.x + threadIdx.x) >> 5;
    int lane = threadIdx.x & 31;
    if (node >= NN) return;
    int s = off[node], e = off[node + 1];
    float4 acc = make_float4(0.f, 0.f, 0.f, 0.f);
    for (int i = s; i < e; i++) {
        int   src = ssrc[i];
        float w   = sw[i];
        uint2 raw = *(const uint2*)(h + (size_t)src * FD + lane * 4);
        float2 f0 = __half22float2(*(__half2*)&raw.x);
        float2 f1 = __half22float2(*(__half2*)&raw.y);
        acc.x = fmaf(w, f0.x, acc.x);
        acc.y = fmaf(w, f0.y, acc.y);
        acc.z = fmaf(w, f1.x, acc.z);
        acc.w = fmaf(w, f1.y, acc.w);
    }
    int self = selfmap ? selfmap[node] : node;
    float id = invd[node];
    uint2 rs = *(const uint2*)(h + (size_t)self * FD + lane * 4);
    float2 s0 = __half22float2(*(__half2*)&rs.x);
    float2 s1 = __half22float2(*(__half2*)&rs.y);
    float4 b = *(const float4*)(bias + lane * 4);
    acc.x = fmaf(id, s0.x, acc.x) + b.x;
    acc.y = fmaf(id, s0.y, acc.y) + b.y;
    acc.z = fmaf(id, s1.x, acc.z) + b.z;
    acc.w = fmaf(id, s1.y, acc.w) + b.w;
    if (dorelu) {
        acc.x = fmaxf(acc.x, 0.f); acc.y = fmaxf(acc.y, 0.f);
        acc.z = fmaxf(acc.z, 0.f); acc.w = fmaxf(acc.w, 0.f);
    }
    __half2 o0 = __floats2half2_rn(acc.x, acc.y);
    __half2 o1 = __floats2half2_rn(acc.z, acc.w);
    *(uint2*)(outh + (size_t)node * FD + lane * 4) =
        make_uint2(*(uint32_t*)&o0, *(uint32_t*)&o1);
}

// ===== fused hop-agg + bilinear score (fp16 G rows) =====
__global__ void k_aggscore(const __half* __restrict__ G, const float* __restrict__ T,
                           const int* __restrict__ off, const int* __restrict__ ssrc,
                           const float* __restrict__ sw, const float* __restrict__ invd,
                           const float* __restrict__ b3, float* __restrict__ out,
                           int col)
{
    const unsigned FULL = 0xffffffffu;
    int node = (blockIdx.x * blockDim.x + threadIdx.x) >> 5;
    int lane = threadIdx.x & 31;
    if (node >= NN) return;
    float4 tv = *(const float4*)(T + (size_t)node * FD + lane * 4);
    int s = off[node], e = off[node + 1];
    float acc = 0.f;
    for (int i = s; i < e; i++) {
        int   src = ssrc[i];
        float w   = sw[i];
        uint2 raw = *(const uint2*)(G + (size_t)src * FD + lane * 4);
        float2 f0 = __half22float2(*(__half2*)&raw.x);
        float2 f1 = __half22float2(*(__half2*)&raw.y);
        acc = fmaf(w, tv.x * f0.x + tv.y * f0.y + tv.z * f1.x + tv.w * f1.y, acc);
    }
    uint2 rs = *(const uint2*)(G + (size_t)node * FD + lane * 4);
    float2 s0 = __half22float2(*(__half2*)&rs.x);
    float2 s1 = __half22float2(*(__half2*)&rs.y);
    float4 bb = *(const float4*)(b3 + lane * 4);
    acc = fmaf(invd[node], tv.x * s0.x + tv.y * s0.y + tv.z * s1.x + tv.w * s1.y, acc);
    acc += tv.x * bb.x + tv.y * bb.y + tv.z * bb.z + tv.w * bb.w;
    #pragma unroll
    for (int d = 16; d > 0; d >>= 1) acc += __shfl_xor_sync(FULL, acc, d);
    if (lane == 0)
        out[(size_t)node * OUTC + col] = 1.0f / (1.0f + expf(-acc));
}

// ================= classifier (reads fp16 P2) =================
__global__ void k_gemm10(const __half* __restrict__ A, const float* __restrict__ W,
                         float* __restrict__ C)
{
    __shared__ float w[FD * NC];
    for (int i = threadIdx.x; i < FD * NC; i += blockDim.x) w[i] = W[i];
    __syncthreads();
    int r = blockIdx.x * blockDim.x + threadIdx.x;
    if (r >= NN) return;
    float acc[NC];
    #pragma unroll
    for (int j = 0; j < NC; j++) acc[j] = 0.f;
    const uint4* ap = (const uint4*)(A + (size_t)r * FD);
    #pragma unroll 4
    for (int k8 = 0; k8 < 16; k8++) {
        uint4 u = ap[k8];
        const __half2* hp = (const __half2*)&u;
        float2 f0 = __half22float2(hp[0]);
        float2 f1 = __half22float2(hp[1]);
        float2 f2 = __half22float2(hp[2]);
        float2 f3 = __half22float2(hp[3]);
        int k = k8 * 8;
        #pragma unroll
        for (int j = 0; j < NC; j++) {
            acc[j] = fmaf(f0.x, w[(k + 0) * NC + j], acc[j]);
            acc[j] = fmaf(f0.y, w[(k + 1) * NC + j], acc[j]);
            acc[j] = fmaf(f1.x, w[(k + 2) * NC + j], acc[j]);
            acc[j] = fmaf(f1.y, w[(k + 3) * NC + j], acc[j]);
            acc[j] = fmaf(f2.x, w[(k + 4) * NC + j], acc[j]);
            acc[j] = fmaf(f2.y, w[(k + 5) * NC + j], acc[j]);
            acc[j] = fmaf(f3.x, w[(k + 6) * NC + j], acc[j]);
            acc[j] = fmaf(f3.y, w[(k + 7) * NC + j], acc[j]);
        }
    }
    #pragma unroll
    for (int j = 0; j < NC; j++) C[(size_t)r * NC + j] = acc[j];
}

__global__ void k_agg10(const float* __restrict__ h, const int* __restrict__ off,
                        const int* __restrict__ ssrc, const float* __restrict__ sw,
                        const float* __restrict__ invd, const float* __restrict__ bc,
                        float* __restrict__ out)
{
    int node = (blockIdx.x * blockDim.x + threadIdx.x) >> 5;
    int lane = threadIdx.x & 31;
    if (node >= NN || lane >= NC) return;
    int s = off[node], e = off[node + 1];
    float acc = 0.f;
    for (int i = s; i < e; i++) {
        int src = ssrc[i];
        acc = fmaf(sw[i], h[(size_t)src * NC + lane], acc);
    }
    acc = fmaf(invd[node], h[(size_t)node * NC + lane], acc) + bc[lane];
    out[(size_t)node * OUTC + lane] = acc;
}

// ================= host =================
extern "C" void kernel_launch(void* const* d_in, const int* in_sizes, int n_in,
                              void* d_out, int out_size)
{
    const float* x    = (const float*)d_in[0];
    const int*   ei   = (const int*)  d_in[1];
    const int*   eh   = (const int*)  d_in[2];
    const int*   perm = (const int*)  d_in[4];
    const float* W1   = (const float*)d_in[5];
    const float* b1   = (const float*)d_in[6];
    const float* W2   = (const float*)d_in[7];
    const float* b2   = (const float*)d_in[8];
    const float* W3   = (const float*)d_in[9];
    const float* b3   = (const float*)d_in[10];
    const float* M1   = (const float*)d_in[11];
    const float* mb1  = (const float*)d_in[12];
    const float* M2   = (const float*)d_in[13];
    const float* mb2  = (const float*)d_in[14];
    const float* Wc   = (const float*)d_in[15];
    const float* bc   = (const float*)d_in[16];
    const float* Wd   = (const float*)d_in[17];
    float* out = (float*)d_out;

    float *T, *C10, *dis, *invd, *sw;
    __half *Hh, *P1, *Gh, *P2, *P3, *P4, *Wf;
    int *cnt, *off, *cur, *btot, *ssrc, *ssrcp;
    cudaGetSymbolAddress((void**)&Hh,   g_Hh);
    cudaGetSymbolAddress((void**)&P1,   g_P1);
    cudaGetSymbolAddress((void**)&Gh,   g_Gh);
    cudaGetSymbolAddress((void**)&P2,   g_P2);
    cudaGetSymbolAddress((void**)&P3,   g_P3);
    cudaGetSymbolAddress((void**)&P4,   g_P4);
    cudaGetSymbolAddress((void**)&T,    g_T);
    cudaGetSymbolAddress((void**)&C10,  g_C10);
    cudaGetSymbolAddress((void**)&Wf,   g_Wf);
    cudaGetSymbolAddress((void**)&cnt,  g_cnt);
    cudaGetSymbolAddress((void**)&dis,  g_dis);
    cudaGetSymbolAddress((void**)&invd, g_invd);
    cudaGetSymbolAddress((void**)&off,  g_off);
    cudaGetSymbolAddress((void**)&cur,  g_cur);
    cudaGetSymbolAddress((void**)&btot, g_btot);
    cudaGetSymbolAddress((void**)&ssrc, g_ssrc);
    cudaGetSymbolAddress((void**)&ssrcp,g_ssrcp);
    cudaGetSymbolAddress((void**)&sw,   g_sw);

    cudaFuncSetAttribute(k_wmma,  cudaFuncAttributeMaxDynamicSharedMemorySize, SMEM_SZ);
    cudaFuncSetAttribute(k_wmmaX, cudaFuncAttributeMaxDynamicSharedMemorySize, XSMEM);

    const int TE  = 256;
    const int GN  = (NN + TE - 1) / TE;
    const int GE2 = (2 * NE + TE - 1) / TE;
    const int GW  = (NN * 32 + TE - 1) / TE;
    const int GM  = (NN + 127) / 128;
    const int GM2 = (2 * NN + 127) / 128;
    const size_t HB = (size_t)NN * FD;

    // ---- prologue (node 5 = k_wmmaX for ncu) ----
    cudaMemsetAsync(cnt, 0, sizeof(int) * 2 * NN);                 // 1
    k_count2<<<GE2, TE>>>(ei + NE, eh + NE, cnt);                  // 2
    k_prepw<<<(512 * 128 + 255) / 256, 256>>>(W1, Wf + WOFF_W1, 512); // 3
    k_deg2<<<(2 * NN + TE - 1) / TE, TE>>>(cnt, dis, invd);        // 4
    k_wmmaX<<<GM, 256, XSMEM>>>(x, Wf + WOFF_W1, nullptr, 0,
                                nullptr, Hh, NN, 512);             // 5 (ncu)

    // ---- scans + placement (both graphs per launch) ----
    k_scan_blk2<<<2 * NB, SCB>>>(cnt, off, btot);
    k_scan_tot2<<<2, 128>>>(btot, off);
    k_scan_add2<<<2 * GN, TE>>>(off, btot, cur, GN);
    k_place2<<<GE2, TE>>>(ei, eh, dis, cur, ssrc, sw, perm, ssrcp);
    k_prepw5<<<(5 * 128 * 128 + 255) / 256, 256>>>(W2, W3, M1, M2, Wd, Wf);

    // ---- layer1 aggs back-to-back (Hh warm in L2) ----
    k_agg<<<GW, TE>>>(Hh, off, ssrc,  sw, invd, b1, nullptr, P1, 1);
    k_agg<<<GW, TE>>>(Hh, off, ssrcp, sw, invd, b1, perm, P1 + HB, 1);

    // ---- batched W2 GEMM over both halves -> Gh ----
    k_wmma<<<GM2, 256, SMEM_SZ>>>(P1, Wf + WOFF_W2, nullptr, 0,
                                  nullptr, Gh, 2 * NN, 128);

    // ---- good half ----
    k_agg<<<GW, TE>>>(Gh, off, ssrc, sw, invd, b2, nullptr, P2, 1);
    k_wmma<<<GM, 256, SMEM_SZ>>>(P2, Wf + WOFF_M1, mb1, 1, nullptr, P3, NN, 128);
    k_gemm10<<<GN, TE>>>(P2, Wc, C10);
    k_agg10<<<GW, TE>>>(C10, off, ssrc, sw, invd, bc, out);
    k_wmma<<<GM, 256, SMEM_SZ>>>(P3, Wf + WOFF_M2, mb2, 0, nullptr, P4, NN, 128);
    k_wmma<<<GM, 256, SMEM_SZ>>>(P4, Wf + WOFF_WD, nullptr, 0, T, nullptr, NN, 128);
    k_wmma<<<GM, 256, SMEM_SZ>>>(P2, Wf + WOFF_W3, nullptr, 0, nullptr, Gh, NN, 128);
    k_aggscore<<<GW, TE>>>(Gh, T, off + (NN + 1), ssrc + NE, sw + NE, invd + NN,
                           b3, out, 10);

    // ---- bad half ----
    k_agg<<<GW, TE>>>(Gh + HB, off, ssrc, sw, invd, b2, nullptr, P2 + HB, 1);
    k_wmma<<<GM, 256, SMEM_SZ>>>(P2 + HB, Wf + WOFF_W3, nullptr, 0,
                                 nullptr, Gh, NN, 128);
    k_aggscore<<<GW, TE>>>(Gh, T, off + (NN + 1), ssrc + NE, sw + NE, invd + NN,
                           b3, out, 11);
}